// round 9
// baseline (speedup 1.0000x reference)
#include <cuda_runtime.h>

#define Bsz 256
#define Mn 87
#define CLSn 65
#define DLn 128
#define DCn 128
#define DOn 2048
#define BDn 256
#define HWn 49
#define NM (DLn*Mn)

#define OUT_FEAT 0
#define OUT_OUT2 65536
#define OUT_SOFT 82176
#define OUT_PRE 98816
#define OUT_FEATP 115456

__device__ float g_xp[Bsz*DOn];
__device__ float g_featp[Bsz*BDn];
__device__ float g_prescore[Bsz*CLSn];
__device__ float g_vy[Bsz*Mn];
__device__ float g_Wpr[Mn*Mn];
__device__ float g_en[Mn*Mn];
__device__ float g_Wef[DLn*DOn];
__device__ float g_WefT[DOn*DLn];
__device__ float g_bef[DLn];
__device__ float g_T1[BDn*512];
__device__ float g_Wcomb[BDn*DLn];
__device__ float g_biasaug[BDn];
__device__ float g_xl[Bsz*DLn*HWn];
__device__ float g_a[Bsz*Mn*HWn];
__device__ float g_ps[Bsz*DCn*HWn];
__device__ float g_m1[Bsz*NM];
__device__ float g_gb[Bsz*NM];
__device__ float g_m2[Bsz*NM];
__device__ float g_G[2*NM];
__device__ float g_u[Bsz*DLn];

// ---------------- edge prep ----------------
__global__ void k_prep_edge(const float* __restrict__ edge) {
    __shared__ float rs[Mn], di[Mn];
    int t = threadIdx.x;
    if (t < Mn) {
        float r = 0.f, c = 0.f;
        for (int j = 0; j < Mn; j++) { r += edge[t*Mn+j]; c += edge[j*Mn+t]; }
        rs[t] = r; di[t] = rsqrtf(c);
    }
    __syncthreads();
    for (int idx = t; idx < Mn*Mn; idx += blockDim.x) {
        int i = idx / Mn, j = idx % Mn;
        float e = edge[idx];
        g_Wpr[idx] = 0.85f * e / rs[j];
        g_en[idx]  = di[i] * e * di[j];
    }
}

// ---------------- tiled SGEMM: C[m,n]=sum_k A[m,k]*B (TRANSB? B[n,k]:B[k,n]) ----------------
template <bool TRANSB, bool HASBIAS>
__global__ void gemm_tiled(const float* __restrict__ A, const float* __restrict__ B,
                           const float* __restrict__ bias, float* __restrict__ C,
                           int M, int N, int K) {
    __shared__ float As[16][64];
    __shared__ float Bs[16][64];
    int tid = threadIdx.x;
    int m0 = blockIdx.y * 64, n0 = blockIdx.x * 64;
    int tm = (tid >> 4) << 2, tn = (tid & 15) << 2;
    float acc[4][4] = {};
    for (int k0 = 0; k0 < K; k0 += 16) {
        {
            int lk = tid & 15, lm0 = tid >> 4;
            #pragma unroll
            for (int i = 0; i < 4; i++) {
                int lm = lm0 + 16*i, m = m0 + lm;
                As[lk][lm] = (m < M) ? A[(size_t)m*K + k0 + lk] : 0.f;
            }
        }
        if (TRANSB) {
            int lk = tid & 15, ln0 = tid >> 4;
            #pragma unroll
            for (int i = 0; i < 4; i++) {
                int ln = ln0 + 16*i, n = n0 + ln;
                Bs[lk][ln] = (n < N) ? B[(size_t)n*K + k0 + lk] : 0.f;
            }
        } else {
            int ln = tid & 63, lk0 = tid >> 6;
            #pragma unroll
            for (int i = 0; i < 4; i++) {
                int lk = lk0*4 + i, n = n0 + ln;
                Bs[lk][ln] = (n < N) ? B[(size_t)(k0+lk)*N + n] : 0.f;
            }
        }
        __syncthreads();
        #pragma unroll
        for (int kk = 0; kk < 16; kk++) {
            float a4[4], b4[4];
            #pragma unroll
            for (int i = 0; i < 4; i++) a4[i] = As[kk][tm+i];
            #pragma unroll
            for (int j = 0; j < 4; j++) b4[j] = Bs[kk][tn+j];
            #pragma unroll
            for (int i = 0; i < 4; i++)
                #pragma unroll
                for (int j = 0; j < 4; j++) acc[i][j] += a4[i]*b4[j];
        }
        __syncthreads();
    }
    #pragma unroll
    for (int i = 0; i < 4; i++) {
        int m = m0 + tm + i; if (m >= M) continue;
        #pragma unroll
        for (int j = 0; j < 4; j++) {
            int n = n0 + tn + j; if (n >= N) continue;
            float v = acc[i][j];
            if (HASBIAS) v += bias[n];
            C[(size_t)m*N + n] = v;
        }
    }
}

__global__ void k_transpose() {
    int c = blockIdx.x * 256 + threadIdx.x;   // 0..2047
    int o = blockIdx.y;                        // 0..127
    g_WefT[(size_t)c*DLn + o] = g_Wef[(size_t)o*DOn + c];
}

__global__ void k_bef_biasaug(const float* __restrict__ Wo2, const float* __restrict__ bo1,
                              const float* __restrict__ bo2, const float* __restrict__ box1,
                              const float* __restrict__ Wb, const float* __restrict__ box2,
                              const float* __restrict__ bb) {
    int t = threadIdx.x;  // 256
    if (t < DLn) {
        float acc = bo2[t];
        for (int k = 0; k < 512; k++) acc += Wo2[t*512 + k] * bo1[k];
        g_bef[t] = acc;
    }
    {
        float acc = bb[t];
        for (int k = 0; k < 512; k++) acc += g_T1[t*512 + k] * box1[k];
        for (int c = 0; c < DOn; c++) acc += Wb[(size_t)t*DOn + c] * box2[c];
        g_biasaug[t] = acc;
    }
}

// ---------------- spatial mean of x ----------------
__global__ void k_xp(const float* __restrict__ x) {
    int gw = (blockIdx.x * blockDim.x + threadIdx.x) >> 5;
    int lane = threadIdx.x & 31;
    const float* row = x + (size_t)gw * HWn;
    float v = (lane < HWn) ? row[lane] : 0.f;
    if (lane + 32 < HWn) v += row[lane + 32];
    #pragma unroll
    for (int o = 16; o; o >>= 1) v += __shfl_down_sync(0xffffffffu, v, o);
    if (lane == 0) g_xp[gw] = v * (1.0f/49.0f);
}

// ---------------- pre_output + softmax ----------------
__global__ void k_preout(const float* __restrict__ Wfc, float* __restrict__ out) {
    int b = blockIdx.x, t = threadIdx.x;  // 256
    __shared__ float f[BDn];
    __shared__ float lg[CLSn];
    __shared__ float mx, sm;
    f[t] = g_featp[b*BDn + t];
    __syncthreads();
    if (t < CLSn) {
        float acc = 0.f;
        const float* w = Wfc + t*BDn;
        for (int c = 0; c < BDn; c++) acc += w[c]*f[c];
        lg[t] = acc;
        out[OUT_PRE + b*CLSn + t] = acc;
    }
    __syncthreads();
    if (t == 0) { float m = -1e30f; for (int i = 0; i < CLSn; i++) m = fmaxf(m, lg[i]); mx = m; }
    __syncthreads();
    if (t < CLSn) lg[t] = expf(lg[t] - mx);
    __syncthreads();
    if (t == 0) { float s = 0.f; for (int i = 0; i < CLSn; i++) s += lg[i]; sm = s; }
    __syncthreads();
    if (t < CLSn) g_prescore[b*CLSn + t] = lg[t] / sm;
}

// ---------------- PageRank: one block (128 thr) per batch ----------------
__global__ void k_pagerank() {
    const int b = blockIdx.x, t = threadIdx.x;
    __shared__ float W[Mn*89];
    __shared__ float v0s[Mn], xA[Mn], xB[Mn];
    __shared__ float red[4];
    __shared__ float zx;
    for (int idx = t; idx < Mn*Mn; idx += 128)
        W[(idx/Mn)*89 + (idx%Mn)] = g_Wpr[idx];
    float vi = 0.f;
    if (t < Mn) {
        vi = (t >= Mn - CLSn) ? g_prescore[b*CLSn + (t - (Mn - CLSn))] : 0.f;
        v0s[t] = vi;
        xA[t] = vi * 87.f;
    }
    __syncthreads();
    const float s87 = vi * 87.f;
    const float coef = 0.15f / 87.f;
    for (int it = 0; it < 100; it++) {
        float* cur = (it & 1) ? xB : xA;
        float* nxt = (it & 1) ? xA : xB;
        float v = (t < Mn) ? cur[t] : 0.f;
        #pragma unroll
        for (int o = 16; o; o >>= 1) v += __shfl_down_sync(0xffffffffu, v, o);
        if ((t & 31) == 0) red[t >> 5] = v;
        __syncthreads();
        if (t == 0) zx = coef * (red[0] + red[1] + red[2] + red[3]);
        __syncthreads();
        if (t < Mn) {
            const float* wr = &W[t*89];
            float a0 = 0.f, a1 = 0.f, a2 = 0.f;
            #pragma unroll
            for (int j = 0; j < 84; j += 3) {
                a0 += wr[j]*cur[j]; a1 += wr[j+1]*cur[j+1]; a2 += wr[j+2]*cur[j+2];
            }
            a0 += wr[84]*cur[84]; a1 += wr[85]*cur[85]; a2 += wr[86]*cur[86];
            nxt[t] = (a0 + a1 + a2) + s87 * zx;
        }
        __syncthreads();
    }
    float xf = (t < Mn) ? xA[t] : 0.f;
    float v2 = xf*xf;
    #pragma unroll
    for (int o = 16; o; o >>= 1) v2 += __shfl_down_sync(0xffffffffu, v2, o);
    if ((t & 31) == 0) red[t >> 5] = v2;
    __syncthreads();
    if (t == 0) zx = sqrtf(red[0] + red[1] + red[2] + red[3]);
    __syncthreads();
    if (t < Mn) g_vy[b*Mn + t] = v0s[t] + xf / fmaxf(zx, 1e-12f);
}

// ---------------- folded conv: x_l = Wef @ x + bef  (M=12544, N=128, K=2048) ----------------
__global__ void conv_xl_kernel(const float* __restrict__ x) {
    __shared__ float As[16][64];
    __shared__ float Bs[16][64];
    int tid = threadIdx.x;
    int m0 = blockIdx.x * 64, n0 = blockIdx.y * 64;
    int tm = (tid >> 4) << 2, tn = (tid & 15) << 2;
    int lm = tid & 63, lk0 = tid >> 6;
    int m = m0 + lm;
    int bb_ = m / HWn, pp_ = m % HWn;
    const float* xbase = x + (size_t)bb_ * (DOn*HWn) + pp_;
    float acc[4][4] = {};
    for (int k0 = 0; k0 < DOn; k0 += 16) {
        #pragma unroll
        for (int i = 0; i < 4; i++) {
            int lk = lk0*4 + i;
            As[lk][lm] = xbase[(size_t)(k0+lk)*HWn];
            Bs[lk][lm] = g_WefT[(size_t)(k0+lk)*DLn + n0 + lm];
        }
        __syncthreads();
        #pragma unroll
        for (int kk = 0; kk < 16; kk++) {
            float a4[4], b4[4];
            #pragma unroll
            for (int i = 0; i < 4; i++) a4[i] = As[kk][tm+i];
            #pragma unroll
            for (int j = 0; j < 4; j++) b4[j] = Bs[kk][tn+j];
            #pragma unroll
            for (int i = 0; i < 4; i++)
                #pragma unroll
                for (int j = 0; j < 4; j++) acc[i][j] += a4[i]*b4[j];
        }
        __syncthreads();
    }
    #pragma unroll
    for (int i = 0; i < 4; i++) {
        int mm = m0 + tm + i;
        int b2 = mm / HWn, p2 = mm % HWn;
        float* dst = g_xl + (size_t)b2*(DLn*HWn) + p2;
        #pragma unroll
        for (int j = 0; j < 4; j++) {
            int o = n0 + tn + j;
            dst[o*HWn] = acc[i][j] + g_bef[o];
        }
    }
}

// ---------------- a (m,p layout) & ps from x_l, per batch ----------------
__global__ void k_aps(const float* __restrict__ Wa, const float* __restrict__ ba,
                      const float* __restrict__ Wps, const float* __restrict__ bps) {
    int b = blockIdx.x, t = threadIdx.x;
    __shared__ float X[DLn*HWn];
    for (int i = t; i < DLn*HWn; i += 256) X[i] = g_xl[(size_t)b*DLn*HWn + i];
    __syncthreads();
    for (int idx = t; idx < (Mn + DCn)*HWn; idx += 256) {
        int rr = idx / HWn, p = idx % HWn;
        const float* w; float bias; float* dst;
        if (rr < Mn) {
            w = Wa + rr*DLn; bias = ba[rr];
            dst = &g_a[(size_t)b*Mn*HWn + rr*HWn + p];
        } else {
            int c = rr - Mn;
            w = Wps + c*DLn; bias = bps[c];
            dst = &g_ps[(size_t)b*DCn*HWn + c*HWn + p];
        }
        float acc = bias;
        #pragma unroll 8
        for (int c = 0; c < DLn; c++) acc += w[c] * X[c*HWn + p];
        *dst = acc;
    }
}

// ---------------- G_e = Wg[:,:128] @ (node_p * v_y_e) : grid(2,4) ----------------
__global__ void k_G(const float* __restrict__ node_p, const float* __restrict__ Wg) {
    int q = blockIdx.x;         // 0,1
    int o0 = blockIdx.y * 32;
    int t = threadIdx.x;        // 256
    __shared__ float Nq[128*88];
    for (int idx = t; idx < 128*Mn; idx += 256) {
        int k = idx / Mn, mm = idx % Mn;
        Nq[k*88 + mm] = node_p[idx] * g_vy[(128*q + k)*Mn + mm];
    }
    __syncthreads();
    for (int idx = t; idx < 32*Mn; idx += 256) {
        int o = o0 + idx / Mn, mm = idx % Mn;
        const float* w = Wg + o*256;
        float acc = 0.f;
        #pragma unroll 8
        for (int k = 0; k < 128; k++) acc += w[k] * Nq[k*88 + mm];
        g_G[q*NM + o*Mn + mm] = acc;
    }
}

// ---------------- m1 = relu(ps @ a), per batch ----------------
__global__ void k_m1() {
    int b = blockIdx.x, t = threadIdx.x;
    __shared__ float psS[DCn*HWn];
    __shared__ float aS[Mn*HWn];
    for (int i = t; i < DCn*HWn; i += 256) psS[i] = g_ps[(size_t)b*DCn*HWn + i];
    for (int i = t; i < Mn*HWn; i += 256)  aS[i]  = g_a[(size_t)b*Mn*HWn + i];
    __syncthreads();
    for (int idx = t; idx < NM; idx += 256) {
        int c = idx / Mn, m = idx % Mn;
        float acc = 0.f;
        #pragma unroll
        for (int p = 0; p < HWn; p++) acc += psS[c*HWn + p] * aS[m*HWn + p];
        g_m1[(size_t)b*NM + idx] = fmaxf(acc, 0.f);
    }
}

// ---------------- g = G_e + Wg2 @ m1 + bg, per batch ----------------
__global__ void k_g(const float* __restrict__ Wg, const float* __restrict__ bg) {
    int b = blockIdx.x, t = threadIdx.x;
    int e = b & 1;
    __shared__ float m1s[128*88];
    for (int i = t; i < NM; i += 256)
        m1s[(i/Mn)*88 + (i%Mn)] = g_m1[(size_t)b*NM + i];
    __syncthreads();
    for (int idx = t; idx < NM; idx += 256) {
        int o = idx / Mn, m = idx % Mn;
        const float* w = Wg + o*256 + 128;
        float acc = g_G[e*NM + idx] + bg[o];
        #pragma unroll 8
        for (int c = 0; c < 128; c++) acc += w[c] * m1s[c*88 + m];
        g_gb[(size_t)b*NM + idx] = acc;
    }
}

// ---------------- m2 = relu(g @ edge_norm), per batch ----------------
__global__ void k_m2() {
    int b = blockIdx.x, t = threadIdx.x;
    __shared__ float gs[128*88];
    for (int i = t; i < NM; i += 256)
        gs[(i/Mn)*88 + (i%Mn)] = g_gb[(size_t)b*NM + i];
    __syncthreads();
    for (int idx = t; idx < NM; idx += 256) {
        int c = idx / Mn, n = idx % Mn;
        float acc = 0.f;
        #pragma unroll
        for (int m = 0; m < Mn; m++) acc += gs[c*88 + m] * g_en[m*Mn + n];
        g_m2[(size_t)b*NM + idx] = fmaxf(acc, 0.f);
    }
}

// ---------------- t_node -> softmax w -> r = m2@w -> u = relu(Wsp@r+bsp), per batch ----------------
__global__ void k_su(const float* __restrict__ Ws, const float* __restrict__ Wsp,
                     const float* __restrict__ bsp) {
    int b = blockIdx.x, t = threadIdx.x;
    __shared__ float m2s[128*88];
    __shared__ float w[Mn];
    __shared__ float rs[128];
    __shared__ float mx, sm;
    for (int i = t; i < NM; i += 256)
        m2s[(i/Mn)*88 + (i%Mn)] = g_m2[(size_t)b*NM + i];
    __syncthreads();
    if (t < Mn) {
        float acc = 0.f;
        #pragma unroll 8
        for (int c = 0; c < 128; c++) acc += Ws[c] * m2s[c*88 + t];
        w[t] = acc;
    }
    __syncthreads();
    if (t == 0) { float m = -1e30f; for (int i = 0; i < Mn; i++) m = fmaxf(m, w[i]); mx = m; }
    __syncthreads();
    if (t < Mn) w[t] = expf(w[t] - mx);
    __syncthreads();
    if (t == 0) { float s = 0.f; for (int i = 0; i < Mn; i++) s += w[i]; sm = s; }
    __syncthreads();
    if (t < Mn) w[t] /= sm;
    __syncthreads();
    if (t < 128) {
        float acc = 0.f;
        #pragma unroll
        for (int m = 0; m < Mn; m++) acc += m2s[t*88 + m] * w[m];
        rs[t] = acc;
    }
    __syncthreads();
    if (t < 128) {
        float acc = bsp[t];
        const float* wr = Wsp + t*128;
        #pragma unroll 8
        for (int c = 0; c < 128; c++) acc += wr[c] * rs[c];
        g_u[b*128 + t] = fmaxf(acc, 0.f);
    }
}

// ---------------- head: features, outputs2, softmax, features_p ----------------
__global__ void k_head(const float* __restrict__ Wfc2, float* __restrict__ out) {
    int b = blockIdx.x, t = threadIdx.x;  // 256
    __shared__ float us[128];
    __shared__ float feat[BDn];
    __shared__ float lg[CLSn];
    __shared__ float mx, sm;
    if (t < 128) us[t] = g_u[b*128 + t];
    __syncthreads();
    {
        float fp = g_featp[b*BDn + t];
        float acc = g_biasaug[t] + fp;
        const float* w = g_Wcomb + t*128;
        #pragma unroll 8
        for (int c = 0; c < 128; c++) acc += w[c] * us[c];
        feat[t] = acc;
        out[OUT_FEAT + b*BDn + t] = acc;
        out[OUT_FEATP + b*BDn + t] = fp;
    }
    __syncthreads();
    if (t < CLSn) {
        float acc = 0.f;
        const float* w = Wfc2 + t*BDn;
        #pragma unroll 8
        for (int c = 0; c < BDn; c++) acc += w[c] * feat[c];
        lg[t] = acc;
        out[OUT_OUT2 + b*CLSn + t] = acc;
    }
    __syncthreads();
    if (t == 0) { float m = -1e30f; for (int i = 0; i < CLSn; i++) m = fmaxf(m, lg[i]); mx = m; }
    __syncthreads();
    if (t < CLSn) lg[t] = expf(lg[t] - mx);
    __syncthreads();
    if (t == 0) { float s = 0.f; for (int i = 0; i < CLSn; i++) s += lg[i]; sm = s; }
    __syncthreads();
    if (t < CLSn) out[OUT_SOFT + b*CLSn + t] = lg[t] / sm;
}

extern "C" void kernel_launch(void* const* d_in, const int* in_sizes, int n_in,
                              void* d_out, int out_size) {
    const float* x     = (const float*)d_in[0];
    const float* Wb    = (const float*)d_in[1];
    const float* bb    = (const float*)d_in[2];
    const float* Wfc   = (const float*)d_in[3];
    const float* Wfc2  = (const float*)d_in[4];
    const float* Wo1   = (const float*)d_in[5];
    const float* bo1   = (const float*)d_in[6];
    const float* Wo2   = (const float*)d_in[7];
    const float* bo2   = (const float*)d_in[8];
    const float* Wa    = (const float*)d_in[9];
    const float* ba    = (const float*)d_in[10];
    const float* Wps   = (const float*)d_in[11];
    const float* bps   = (const float*)d_in[12];
    const float* node_p= (const float*)d_in[13];
    const float* Wg    = (const float*)d_in[14];
    const float* bg    = (const float*)d_in[15];
    const float* Wsp   = (const float*)d_in[16];
    const float* bsp   = (const float*)d_in[17];
    const float* Ws    = (const float*)d_in[18];
    const float* Wox1  = (const float*)d_in[20];
    const float* box1  = (const float*)d_in[21];
    const float* Wox2  = (const float*)d_in[22];
    const float* box2  = (const float*)d_in[23];
    const float* edge  = (const float*)d_in[24];
    float* out = (float*)d_out;

    float* pWef   = nullptr; cudaGetSymbolAddress((void**)&pWef,   g_Wef);
    float* pT1    = nullptr; cudaGetSymbolAddress((void**)&pT1,    g_T1);
    float* pWcomb = nullptr; cudaGetSymbolAddress((void**)&pWcomb, g_Wcomb);
    float* pXp    = nullptr; cudaGetSymbolAddress((void**)&pXp,    g_xp);
    float* pFeatp = nullptr; cudaGetSymbolAddress((void**)&pFeatp, g_featp);

    // edge prep
    k_prep_edge<<<1, 256>>>(edge);
    // Wef = Wo2 @ Wo1  (128 x 2048, K=512)
    gemm_tiled<false,false><<<dim3(32,2), 256>>>(Wo2, Wo1, nullptr, pWef, 128, 2048, 512);
    k_transpose<<<dim3(8,128), 256>>>();
    // T1 = Wb @ Wox2  (256 x 512, K=2048)
    gemm_tiled<false,false><<<dim3(8,4), 256>>>(Wb, Wox2, nullptr, pT1, 256, 512, 2048);
    // Wcomb = T1 @ Wox1  (256 x 128, K=512)
    gemm_tiled<false,false><<<dim3(2,4), 256>>>(pT1, Wox1, nullptr, pWcomb, 256, 128, 512);
    k_bef_biasaug<<<1, 256>>>(Wo2, bo1, bo2, box1, Wb, box2, bb);
    // spatial mean of x
    k_xp<<<65536, 256>>>(x);
    // features_p = x_p @ Wb^T + bb
    gemm_tiled<true,true><<<dim3(4,4), 256>>>(pXp, Wb, bb, pFeatp, 256, 256, 2048);
    k_preout<<<256, 256>>>(Wfc, out);
    k_pagerank<<<256, 128>>>();
    // x_l
    conv_xl_kernel<<<dim3(196,2), 256>>>(x);
    k_aps<<<256, 256>>>(Wa, ba, Wps, bps);
    k_G<<<dim3(2,4), 256>>>(node_p, Wg);
    k_m1<<<256, 256>>>();
    k_g<<<256, 256>>>(Wg, bg);
    k_m2<<<256, 256>>>();
    k_su<<<256, 256>>>(Ws, Wsp, bsp);
    k_head<<<256, 256>>>(Wfc2, out);
}

// round 10
// speedup vs baseline: 1.3121x; 1.3121x over previous
#include <cuda_runtime.h>

#define Bsz 256
#define Mn 87
#define CLSn 65
#define DLn 128
#define DOn 2048
#define BDn 256
#define HWn 49
#define NM (DLn*Mn)

#define OUT_FEAT 0
#define OUT_OUT2 65536
#define OUT_SOFT 82176
#define OUT_PRE 98816
#define OUT_FEATP 115456

__device__ float g_xp[Bsz*DOn];
__device__ float g_featp[Bsz*BDn];
__device__ float g_prescore[Bsz*CLSn];
__device__ float g_vy[Bsz*Mn];
__device__ float g_Wpr[Mn*Mn];
__device__ float g_en[Mn*Mn];
__device__ float g_WefT[DOn*DLn];
__device__ float g_bef[DLn];
__device__ float g_Z[DOn*DLn];
__device__ float g_v1[DOn];
__device__ float g_Wcomb[BDn*DLn];
__device__ float g_biasaug[BDn];
__device__ float g_part[4*BDn*BDn];
__device__ float g_xl2[Bsz*HWn*DLn];
__device__ float g_a[Bsz*Mn*HWn];
__device__ float g_ps[Bsz*DLn*HWn];
__device__ float g_m1[Bsz*NM];
__device__ float g_gb[Bsz*NM];
__device__ float g_m2[Bsz*NM];
__device__ float g_G[2*NM];
__device__ float g_u[Bsz*DLn];

// ---------------- edge prep ----------------
__global__ void k_prep_edge(const float* __restrict__ edge) {
    __shared__ float rs[Mn], di[Mn];
    int t = threadIdx.x;
    if (t < Mn) {
        float r = 0.f, c = 0.f;
        for (int j = 0; j < Mn; j++) { r += edge[t*Mn+j]; c += edge[j*Mn+t]; }
        rs[t] = r; di[t] = rsqrtf(c);
    }
    __syncthreads();
    for (int idx = t; idx < Mn*Mn; idx += blockDim.x) {
        int i = idx / Mn, j = idx % Mn;
        float e = edge[idx];
        g_Wpr[idx] = 0.85f * e / rs[j];
        g_en[idx]  = di[i] * e * di[j];
    }
}

// ---------------- double-buffered 64x64x16 SGEMM ----------------
// MA==0: A row-major M*K.  MA==1: A k-major K*M.
// MB==0: B k-major K*N.    MB==1: B row-major N*K.
// SPLIT: write partial slab per blockIdx.z (K sliced evenly).
template<int MA, int MB, bool SPLIT>
__global__ void gemm_db(const float* __restrict__ A, const float* __restrict__ B,
                        float* __restrict__ C, int M, int N, int K) {
    __shared__ float As[2][16][68];
    __shared__ float Bs[2][16][68];
    const int tid = threadIdx.x;
    const int m0 = blockIdx.x*64, n0 = blockIdx.y*64;
    int kb = 0, kn = K;
    if (SPLIT) { kn = K / gridDim.z; kb = blockIdx.z * kn; }
    const int nt = kn >> 4;
    const int tm = (tid>>4)<<2, tn = (tid&15)<<2;
    int a_r, a_c, b_r, b_c;
    if (MA==0) { a_r = tid>>2; a_c = (tid&3)<<2; }
    else       { a_r = tid>>4; a_c = (tid&15)<<2; }
    if (MB==0) { b_r = tid>>4; b_c = (tid&15)<<2; }
    else       { b_r = tid>>2; b_c = (tid&3)<<2; }
    float acc[4][4] = {};
    float ra[4], rb[4];
    auto LD = [&](int k0){
        float4 va, vb;
        if (MA==0) va = *(const float4*)&A[(size_t)(m0+a_r)*K + k0 + a_c];
        else       va = *(const float4*)&A[(size_t)(k0+a_r)*M + m0 + a_c];
        if (MB==0) vb = *(const float4*)&B[(size_t)(k0+b_r)*N + n0 + b_c];
        else       vb = *(const float4*)&B[(size_t)(n0+b_r)*K + k0 + b_c];
        ra[0]=va.x; ra[1]=va.y; ra[2]=va.z; ra[3]=va.w;
        rb[0]=vb.x; rb[1]=vb.y; rb[2]=vb.z; rb[3]=vb.w;
    };
    auto ST = [&](int buf){
        if (MA==0) {
            As[buf][a_c+0][a_r]=ra[0]; As[buf][a_c+1][a_r]=ra[1];
            As[buf][a_c+2][a_r]=ra[2]; As[buf][a_c+3][a_r]=ra[3];
        } else {
            *(float4*)&As[buf][a_r][a_c] = make_float4(ra[0],ra[1],ra[2],ra[3]);
        }
        if (MB==0) {
            *(float4*)&Bs[buf][b_r][b_c] = make_float4(rb[0],rb[1],rb[2],rb[3]);
        } else {
            Bs[buf][b_c+0][b_r]=rb[0]; Bs[buf][b_c+1][b_r]=rb[1];
            Bs[buf][b_c+2][b_r]=rb[2]; Bs[buf][b_c+3][b_r]=rb[3];
        }
    };
    LD(kb); ST(0); __syncthreads();
    for (int t = 0; t < nt; t++) {
        int cur = t & 1;
        if (t+1 < nt) LD(kb + ((t+1)<<4));
        #pragma unroll
        for (int kk = 0; kk < 16; kk++) {
            float4 a4 = *(const float4*)&As[cur][kk][tm];
            float4 b4 = *(const float4*)&Bs[cur][kk][tn];
            float av[4]={a4.x,a4.y,a4.z,a4.w}, bv[4]={b4.x,b4.y,b4.z,b4.w};
            #pragma unroll
            for (int i=0;i<4;i++)
                #pragma unroll
                for (int j=0;j<4;j++) acc[i][j] += av[i]*bv[j];
        }
        if (t+1 < nt) { ST(1-cur); __syncthreads(); }
    }
    float* dst = SPLIT ? (C + (size_t)blockIdx.z*M*N) : C;
    #pragma unroll
    for (int i=0;i<4;i++) {
        float4 v = make_float4(acc[i][0],acc[i][1],acc[i][2],acc[i][3]);
        *(float4*)&dst[(size_t)(m0+tm+i)*N + n0+tn] = v;
    }
}

// ---------------- reduce split-K partials (+optional bias over n) ----------------
__global__ void k_reduce(const float* __restrict__ P, const float* __restrict__ bias,
                         float* __restrict__ C, int MN, int N, int Z) {
    int i = blockIdx.x*256 + threadIdx.x;
    if (i >= MN) return;
    float s = 0.f;
    for (int z = 0; z < Z; z++) s += P[(size_t)z*MN + i];
    if (bias) s += bias[i % N];
    C[i] = s;
}

// ---------------- v1 = Wox2@box1 ; bef = Wo2@bo1 + bo2 (warp per output) ----------------
__global__ void k_bias1(const float* __restrict__ Wox2, const float* __restrict__ box1,
                        const float* __restrict__ Wo2, const float* __restrict__ bo1,
                        const float* __restrict__ bo2) {
    int wid = blockIdx.x*8 + (threadIdx.x>>5);
    int lane = threadIdx.x & 31;
    if (wid < 2048) {
        float s = 0.f;
        #pragma unroll
        for (int it=0; it<4; it++) {
            int k = (lane + 32*it) << 2;
            float4 w = *(const float4*)&Wox2[(size_t)wid*512 + k];
            float4 b = *(const float4*)&box1[k];
            s += w.x*b.x + w.y*b.y + w.z*b.z + w.w*b.w;
        }
        #pragma unroll
        for (int o=16;o;o>>=1) s += __shfl_down_sync(0xffffffffu, s, o);
        if (lane==0) g_v1[wid] = s;
    } else if (wid < 2176) {
        int o = wid - 2048;
        float s = 0.f;
        #pragma unroll
        for (int it=0; it<4; it++) {
            int k = (lane + 32*it) << 2;
            float4 w = *(const float4*)&Wo2[(size_t)o*512 + k];
            float4 b = *(const float4*)&bo1[k];
            s += w.x*b.x + w.y*b.y + w.z*b.z + w.w*b.w;
        }
        #pragma unroll
        for (int sh=16;sh;sh>>=1) s += __shfl_down_sync(0xffffffffu, s, sh);
        if (lane==0) g_bef[o] = bo2[o] + s;
    }
}

// ---------------- biasaug = bb + Wb@(v1+box2) ----------------
__global__ void k_bias2(const float* __restrict__ Wb, const float* __restrict__ box2,
                        const float* __restrict__ bb) {
    int o = blockIdx.x*8 + (threadIdx.x>>5);
    int lane = threadIdx.x & 31;
    float s = 0.f;
    #pragma unroll
    for (int it=0; it<16; it++) {
        int k = (lane + 32*it) << 2;
        float4 w  = *(const float4*)&Wb[(size_t)o*2048 + k];
        float4 v  = *(const float4*)&g_v1[k];
        float4 b2 = *(const float4*)&box2[k];
        s += w.x*(v.x+b2.x) + w.y*(v.y+b2.y) + w.z*(v.z+b2.z) + w.w*(v.w+b2.w);
    }
    #pragma unroll
    for (int sh=16;sh;sh>>=1) s += __shfl_down_sync(0xffffffffu, s, sh);
    if (lane==0) g_biasaug[o] = bb[o] + s;
}

// ---------------- spatial mean of x ----------------
__global__ void k_xp(const float* __restrict__ x) {
    int gw = (blockIdx.x * blockDim.x + threadIdx.x) >> 5;
    int lane = threadIdx.x & 31;
    const float* row = x + (size_t)gw * HWn;
    float v = (lane < HWn) ? row[lane] : 0.f;
    if (lane + 32 < HWn) v += row[lane + 32];
    #pragma unroll
    for (int o = 16; o; o >>= 1) v += __shfl_down_sync(0xffffffffu, v, o);
    if (lane == 0) g_xp[gw] = v * (1.0f/49.0f);
}

// ---------------- pre_output + softmax ----------------
__global__ void k_preout(const float* __restrict__ Wfc, float* __restrict__ out) {
    int b = blockIdx.x, t = threadIdx.x;
    __shared__ float f[BDn];
    __shared__ float lg[CLSn];
    __shared__ float mx, sm;
    f[t] = g_featp[b*BDn + t];
    __syncthreads();
    if (t < CLSn) {
        float acc = 0.f;
        const float* w = Wfc + t*BDn;
        for (int c = 0; c < BDn; c++) acc += w[c]*f[c];
        lg[t] = acc;
        out[OUT_PRE + b*CLSn + t] = acc;
    }
    __syncthreads();
    if (t == 0) { float m = -1e30f; for (int i = 0; i < CLSn; i++) m = fmaxf(m, lg[i]); mx = m; }
    __syncthreads();
    if (t < CLSn) lg[t] = expf(lg[t] - mx);
    __syncthreads();
    if (t == 0) { float s = 0.f; for (int i = 0; i < CLSn; i++) s += lg[i]; sm = s; }
    __syncthreads();
    if (t < CLSn) g_prescore[b*CLSn + t] = lg[t] / sm;
}

// ---------------- PageRank: one block (128 thr) per batch ----------------
__global__ void k_pagerank() {
    const int b = blockIdx.x, t = threadIdx.x;
    __shared__ float W[Mn*89];
    __shared__ float v0s[Mn], xA[Mn], xB[Mn];
    __shared__ float red[4];
    __shared__ float zx;
    for (int idx = t; idx < Mn*Mn; idx += 128)
        W[(idx/Mn)*89 + (idx%Mn)] = g_Wpr[idx];
    float vi = 0.f;
    if (t < Mn) {
        vi = (t >= Mn - CLSn) ? g_prescore[b*CLSn + (t - (Mn - CLSn))] : 0.f;
        v0s[t] = vi;
        xA[t] = vi * 87.f;
    }
    __syncthreads();
    const float s87 = vi * 87.f;
    const float coef = 0.15f / 87.f;
    for (int it = 0; it < 100; it++) {
        float* cur = (it & 1) ? xB : xA;
        float* nxt = (it & 1) ? xA : xB;
        float v = (t < Mn) ? cur[t] : 0.f;
        #pragma unroll
        for (int o = 16; o; o >>= 1) v += __shfl_down_sync(0xffffffffu, v, o);
        if ((t & 31) == 0) red[t >> 5] = v;
        __syncthreads();
        if (t == 0) zx = coef * (red[0] + red[1] + red[2] + red[3]);
        __syncthreads();
        if (t < Mn) {
            const float* wr = &W[t*89];
            float a0 = 0.f, a1 = 0.f, a2 = 0.f;
            #pragma unroll
            for (int j = 0; j < 84; j += 3) {
                a0 += wr[j]*cur[j]; a1 += wr[j+1]*cur[j+1]; a2 += wr[j+2]*cur[j+2];
            }
            a0 += wr[84]*cur[84]; a1 += wr[85]*cur[85]; a2 += wr[86]*cur[86];
            nxt[t] = (a0 + a1 + a2) + s87 * zx;
        }
        __syncthreads();
    }
    float xf = (t < Mn) ? xA[t] : 0.f;
    float v2 = xf*xf;
    #pragma unroll
    for (int o = 16; o; o >>= 1) v2 += __shfl_down_sync(0xffffffffu, v2, o);
    if ((t & 31) == 0) red[t >> 5] = v2;
    __syncthreads();
    if (t == 0) zx = sqrtf(red[0] + red[1] + red[2] + red[3]);
    __syncthreads();
    if (t < Mn) g_vy[b*Mn + t] = v0s[t] + xf / fmaxf(zx, 1e-12f);
}

// ---------------- conv: xl2[(b,p)][c] = (Wef @ x)[(b,p)][c] + bef[c], DB ----------------
__global__ void conv_xl_db(const float* __restrict__ x) {
    __shared__ float As[2][16][68];
    __shared__ float Bs[2][16][68];
    const int tid = threadIdx.x;
    const int m0 = blockIdx.x*64, n0 = blockIdx.y*64;
    const int tm = (tid>>4)<<2, tn = (tid&15)<<2;
    const int lm = tid & 63, lk0 = (tid>>6)<<2;
    const int m = m0 + lm;
    const float* xb = x + (size_t)(m/HWn)*(DOn*HWn) + (m%HWn);
    const int b_r = tid>>4, b_c = (tid&15)<<2;
    float acc[4][4] = {};
    float ra[4], rb[4];
    auto LD = [&](int k0){
        #pragma unroll
        for (int i=0;i<4;i++) ra[i] = xb[(size_t)(k0+lk0+i)*HWn];
        float4 vb = *(const float4*)&g_WefT[(size_t)(k0+b_r)*DLn + n0 + b_c];
        rb[0]=vb.x; rb[1]=vb.y; rb[2]=vb.z; rb[3]=vb.w;
    };
    auto ST = [&](int buf){
        #pragma unroll
        for (int i=0;i<4;i++) As[buf][lk0+i][lm]=ra[i];
        *(float4*)&Bs[buf][b_r][b_c] = make_float4(rb[0],rb[1],rb[2],rb[3]);
    };
    LD(0); ST(0); __syncthreads();
    const int nt = DOn/16;
    for (int t=0;t<nt;t++){
        int cur=t&1;
        if (t+1<nt) LD((t+1)<<4);
        #pragma unroll
        for (int kk=0;kk<16;kk++){
            float4 a4 = *(const float4*)&As[cur][kk][tm];
            float4 b4 = *(const float4*)&Bs[cur][kk][tn];
            float av[4]={a4.x,a4.y,a4.z,a4.w}, bv[4]={b4.x,b4.y,b4.z,b4.w};
            #pragma unroll
            for (int i=0;i<4;i++)
                #pragma unroll
                for (int j=0;j<4;j++) acc[i][j] += av[i]*bv[j];
        }
        if (t+1<nt){ ST(1-cur); __syncthreads(); }
    }
    float4 bf = *(const float4*)&g_bef[n0+tn];
    #pragma unroll
    for (int i=0;i<4;i++){
        float4 v = make_float4(acc[i][0]+bf.x, acc[i][1]+bf.y, acc[i][2]+bf.z, acc[i][3]+bf.w);
        *(float4*)&g_xl2[(size_t)(m0+tm+i)*DLn + n0+tn] = v;
    }
}

// ---------------- a[m][p] & ps[c][p] from xl2 ([p][c] per batch) ----------------
__global__ void k_aps(const float* __restrict__ Wa, const float* __restrict__ ba,
                      const float* __restrict__ Wps, const float* __restrict__ bps) {
    int b = blockIdx.x, t = threadIdx.x;
    __shared__ float X[HWn*DLn];
    {
        const float4* src = (const float4*)(g_xl2 + (size_t)b*HWn*DLn);
        for (int i = t; i < HWn*DLn/4; i += 256) ((float4*)X)[i] = src[i];
    }
    __syncthreads();
    for (int idx = t; idx < (Mn + DLn)*HWn; idx += 256) {
        int rr = idx / HWn, p = idx % HWn;
        const float* w; float bias; float* dst;
        if (rr < Mn) {
            w = Wa + rr*DLn; bias = ba[rr];
            dst = &g_a[(size_t)b*Mn*HWn + rr*HWn + p];
        } else {
            int c = rr - Mn;
            w = Wps + c*DLn; bias = bps[c];
            dst = &g_ps[(size_t)b*DLn*HWn + c*HWn + p];
        }
        float acc = bias;
        const float4* w4 = (const float4*)w;
        const float4* x4 = (const float4*)&X[p*DLn];
        #pragma unroll 8
        for (int c4 = 0; c4 < 32; c4++) {
            float4 wv = w4[c4], xv = x4[c4];
            acc += wv.x*xv.x + wv.y*xv.y + wv.z*xv.z + wv.w*xv.w;
        }
        *dst = acc;
    }
}

// ---------------- G_e = Wg[:,:128] @ (node_p * v_y_e) ----------------
__global__ void k_G(const float* __restrict__ node_p, const float* __restrict__ Wg) {
    int q = blockIdx.x;
    int o0 = blockIdx.y * 32;
    int t = threadIdx.x;
    __shared__ float Nq[128*88];
    for (int idx = t; idx < 128*Mn; idx += 256) {
        int k = idx / Mn, mm = idx % Mn;
        Nq[k*88 + mm] = node_p[idx] * g_vy[(128*q + k)*Mn + mm];
    }
    __syncthreads();
    for (int idx = t; idx < 32*Mn; idx += 256) {
        int o = o0 + idx / Mn, mm = idx % Mn;
        const float* w = Wg + o*256;
        float acc = 0.f;
        #pragma unroll 8
        for (int k = 0; k < 128; k++) acc += w[k] * Nq[k*88 + mm];
        g_G[q*NM + o*Mn + mm] = acc;
    }
}

// ---------------- m1 = relu(ps @ a^T) ----------------
__global__ void k_m1() {
    int b = blockIdx.x, t = threadIdx.x;
    __shared__ float psS[DLn*HWn];
    __shared__ float aS[Mn*HWn];
    for (int i = t; i < DLn*HWn; i += 256) psS[i] = g_ps[(size_t)b*DLn*HWn + i];
    for (int i = t; i < Mn*HWn; i += 256)  aS[i]  = g_a[(size_t)b*Mn*HWn + i];
    __syncthreads();
    for (int idx = t; idx < NM; idx += 256) {
        int c = idx / Mn, m = idx % Mn;
        float acc = 0.f;
        #pragma unroll
        for (int p = 0; p < HWn; p++) acc += psS[c*HWn + p] * aS[m*HWn + p];
        g_m1[(size_t)b*NM + idx] = fmaxf(acc, 0.f);
    }
}

// ---------------- g = G_e + Wg2 @ m1 + bg ----------------
__global__ void k_g(const float* __restrict__ Wg, const float* __restrict__ bg) {
    int b = blockIdx.x, t = threadIdx.x;
    int e = b & 1;
    __shared__ float m1s[128*88];
    for (int i = t; i < NM; i += 256)
        m1s[(i/Mn)*88 + (i%Mn)] = g_m1[(size_t)b*NM + i];
    __syncthreads();
    for (int idx = t; idx < NM; idx += 256) {
        int o = idx / Mn, m = idx % Mn;
        const float* w = Wg + o*256 + 128;
        float acc = g_G[e*NM + idx] + bg[o];
        #pragma unroll 8
        for (int c = 0; c < 128; c++) acc += w[c] * m1s[c*88 + m];
        g_gb[(size_t)b*NM + idx] = acc;
    }
}

// ---------------- m2 = relu(g @ edge_norm) ----------------
__global__ void k_m2() {
    int b = blockIdx.x, t = threadIdx.x;
    __shared__ float gs[128*88];
    for (int i = t; i < NM; i += 256)
        gs[(i/Mn)*88 + (i%Mn)] = g_gb[(size_t)b*NM + i];
    __syncthreads();
    for (int idx = t; idx < NM; idx += 256) {
        int c = idx / Mn, n = idx % Mn;
        float acc = 0.f;
        #pragma unroll
        for (int m = 0; m < Mn; m++) acc += gs[c*88 + m] * g_en[m*Mn + n];
        g_m2[(size_t)b*NM + idx] = fmaxf(acc, 0.f);
    }
}

// ---------------- softmax weights + u ----------------
__global__ void k_su(const float* __restrict__ Ws, const float* __restrict__ Wsp,
                     const float* __restrict__ bsp) {
    int b = blockIdx.x, t = threadIdx.x;
    __shared__ float m2s[128*88];
    __shared__ float w[Mn];
    __shared__ float rs[128];
    __shared__ float mx, sm;
    for (int i = t; i < NM; i += 256)
        m2s[(i/Mn)*88 + (i%Mn)] = g_m2[(size_t)b*NM + i];
    __syncthreads();
    if (t < Mn) {
        float acc = 0.f;
        #pragma unroll 8
        for (int c = 0; c < 128; c++) acc += Ws[c] * m2s[c*88 + t];
        w[t] = acc;
    }
    __syncthreads();
    if (t == 0) { float m = -1e30f; for (int i = 0; i < Mn; i++) m = fmaxf(m, w[i]); mx = m; }
    __syncthreads();
    if (t < Mn) w[t] = expf(w[t] - mx);
    __syncthreads();
    if (t == 0) { float s = 0.f; for (int i = 0; i < Mn; i++) s += w[i]; sm = s; }
    __syncthreads();
    if (t < Mn) w[t] /= sm;
    __syncthreads();
    if (t < 128) {
        float acc = 0.f;
        #pragma unroll
        for (int m = 0; m < Mn; m++) acc += m2s[t*88 + m] * w[m];
        rs[t] = acc;
    }
    __syncthreads();
    if (t < 128) {
        float acc = bsp[t];
        const float* wr = Wsp + t*128;
        #pragma unroll 8
        for (int c = 0; c < 128; c++) acc += wr[c] * rs[c];
        g_u[b*128 + t] = fmaxf(acc, 0.f);
    }
}

// ---------------- head ----------------
__global__ void k_head(const float* __restrict__ Wfc2, float* __restrict__ out) {
    int b = blockIdx.x, t = threadIdx.x;
    __shared__ float us[128];
    __shared__ float feat[BDn];
    __shared__ float lg[CLSn];
    __shared__ float mx, sm;
    if (t < 128) us[t] = g_u[b*128 + t];
    __syncthreads();
    {
        float fp = g_featp[b*BDn + t];
        float acc = g_biasaug[t] + fp;
        const float* w = g_Wcomb + t*128;
        #pragma unroll 8
        for (int c = 0; c < 128; c++) acc += w[c] * us[c];
        feat[t] = acc;
        out[OUT_FEAT + b*BDn + t] = acc;
        out[OUT_FEATP + b*BDn + t] = fp;
    }
    __syncthreads();
    if (t < CLSn) {
        float acc = 0.f;
        const float* w = Wfc2 + t*BDn;
        #pragma unroll 8
        for (int c = 0; c < BDn; c++) acc += w[c] * feat[c];
        lg[t] = acc;
        out[OUT_OUT2 + b*CLSn + t] = acc;
    }
    __syncthreads();
    if (t == 0) { float m = -1e30f; for (int i = 0; i < CLSn; i++) m = fmaxf(m, lg[i]); mx = m; }
    __syncthreads();
    if (t < CLSn) lg[t] = expf(lg[t] - mx);
    __syncthreads();
    if (t == 0) { float s = 0.f; for (int i = 0; i < CLSn; i++) s += lg[i]; sm = s; }
    __syncthreads();
    if (t < CLSn) out[OUT_SOFT + b*CLSn + t] = lg[t] / sm;
}

extern "C" void kernel_launch(void* const* d_in, const int* in_sizes, int n_in,
                              void* d_out, int out_size) {
    const float* x     = (const float*)d_in[0];
    const float* Wb    = (const float*)d_in[1];
    const float* bb    = (const float*)d_in[2];
    const float* Wfc   = (const float*)d_in[3];
    const float* Wfc2  = (const float*)d_in[4];
    const float* Wo1   = (const float*)d_in[5];
    const float* bo1   = (const float*)d_in[6];
    const float* Wo2   = (const float*)d_in[7];
    const float* bo2   = (const float*)d_in[8];
    const float* Wa    = (const float*)d_in[9];
    const float* ba    = (const float*)d_in[10];
    const float* Wps   = (const float*)d_in[11];
    const float* bps   = (const float*)d_in[12];
    const float* node_p= (const float*)d_in[13];
    const float* Wg    = (const float*)d_in[14];
    const float* bg    = (const float*)d_in[15];
    const float* Wsp   = (const float*)d_in[16];
    const float* bsp   = (const float*)d_in[17];
    const float* Ws    = (const float*)d_in[18];
    const float* Wox1  = (const float*)d_in[20];
    const float* box1  = (const float*)d_in[21];
    const float* Wox2  = (const float*)d_in[22];
    const float* box2  = (const float*)d_in[23];
    const float* edge  = (const float*)d_in[24];
    float* out = (float*)d_out;

    float* pWefT  = nullptr; cudaGetSymbolAddress((void**)&pWefT,  g_WefT);
    float* pZ     = nullptr; cudaGetSymbolAddress((void**)&pZ,     g_Z);
    float* pWcomb = nullptr; cudaGetSymbolAddress((void**)&pWcomb, g_Wcomb);
    float* pPart  = nullptr; cudaGetSymbolAddress((void**)&pPart,  g_part);
    float* pXp    = nullptr; cudaGetSymbolAddress((void**)&pXp,    g_xp);
    float* pFeatp = nullptr; cudaGetSymbolAddress((void**)&pFeatp, g_featp);

    k_prep_edge<<<1, 256>>>(edge);
    // WefT[c][o] = sum_j Wo1[j][c]*Wo2[o][j]  (M=2048 c, N=128 o, K=512)
    gemm_db<1,1,false><<<dim3(32,2), 256>>>(Wo1, Wo2, pWefT, 2048, 128, 512);
    // Z = Wox2 @ Wox1  (2048 x 128, K=512)
    gemm_db<0,0,false><<<dim3(32,2), 256>>>(Wox2, Wox1, pZ, 2048, 128, 512);
    // Wcomb = Wb @ Z  (256 x 128, K=2048), split-K x4
    gemm_db<0,0,true><<<dim3(4,2,4), 256>>>(Wb, pZ, pPart, 256, 128, 2048);
    k_reduce<<<(256*128+255)/256, 256>>>(pPart, nullptr, pWcomb, 256*128, 128, 4);
    k_bias1<<<272, 256>>>(Wox2, box1, Wo2, bo1, bo2);
    k_bias2<<<32, 256>>>(Wb, box2, bb);
    k_xp<<<65536, 256>>>(x);
    // featp = xp @ Wb^T + bb  (256 x 256, K=2048), split-K x4
    gemm_db<0,1,true><<<dim3(4,4,4), 256>>>(pXp, Wb, pPart, 256, 256, 2048);
    k_reduce<<<(65536+255)/256, 256>>>(pPart, bb, pFeatp, 65536, 256, 4);
    k_preout<<<256, 256>>>(Wfc, out);
    k_pagerank<<<256, 128>>>();
    conv_xl_db<<<dim3(196,2), 256>>>(x);
    k_aps<<<256, 256>>>(Wa, ba, Wps, bps);
    k_G<<<dim3(2,4), 256>>>(node_p, Wg);
    k_m1<<<256, 256>>>();
    k_g<<<256, 256>>>(Wg, bg);
    k_m2<<<256, 256>>>();
    k_su<<<256, 256>>>(Ws, Wsp, bsp);
    k_head<<<256, 256>>>(Wfc2, out);
}

// round 11
// speedup vs baseline: 2.0330x; 1.5495x over previous
#include <cuda_runtime.h>

#define Bsz 256
#define Mn 87
#define CLSn 65
#define DLn 128
#define DOn 2048
#define BDn 256
#define HWn 49
#define NM (DLn*Mn)
#define NPIX (Bsz*HWn)

#define OUT_FEAT 0
#define OUT_OUT2 65536
#define OUT_SOFT 82176
#define OUT_PRE 98816
#define OUT_FEATP 115456

__device__ float g_xp[Bsz*DOn];
__device__ float g_featp[Bsz*BDn];
__device__ float g_prescore[Bsz*CLSn];
__device__ float g_vy[Bsz*Mn];
__device__ float g_Wpr[Mn*Mn];
__device__ float g_en[Mn*Mn];
__device__ float g_WefT[DOn*DLn];
__device__ float g_bef[DLn];
__device__ float g_Z[DOn*DLn];
__device__ float g_v1[DOn];
__device__ float g_Wcomb[BDn*DLn];
__device__ float g_biasaug[BDn];
__device__ float g_part[8*BDn*BDn];
__device__ float g_xl2[NPIX*DLn];
__device__ float g_Wap[256*DLn];
__device__ float g_Wg2T[DLn*DLn];
__device__ float g_aps[256*NPIX];
__device__ float g_G[2*NM];
__device__ float g_u[Bsz*DLn];

// ---------------- edge prep ----------------
__global__ void k_prep_edge(const float* __restrict__ edge) {
    __shared__ float rs[Mn], di[Mn];
    int t = threadIdx.x;
    if (t < Mn) {
        float r = 0.f, c = 0.f;
        for (int j = 0; j < Mn; j++) { r += edge[t*Mn+j]; c += edge[j*Mn+t]; }
        rs[t] = r; di[t] = rsqrtf(c);
    }
    __syncthreads();
    for (int idx = t; idx < Mn*Mn; idx += blockDim.x) {
        int i = idx / Mn, j = idx % Mn;
        float e = edge[idx];
        g_Wpr[idx] = 0.85f * e / rs[j];
        g_en[idx]  = di[i] * e * di[j];
    }
}

// ---------------- Wap pad + Wg2 transpose ----------------
__global__ void k_prep2(const float* __restrict__ Wa, const float* __restrict__ Wps,
                        const float* __restrict__ Wg) {
    int i = blockIdx.x*256 + threadIdx.x;
    if (i < 256*128) {
        int m = i >> 7, c = i & 127;
        float v = 0.f;
        if (m < Mn) v = Wa[m*128 + c];
        else if (m >= 128) v = Wps[(m-128)*128 + c];
        g_Wap[i] = v;
    } else if (i < 256*128 + 128*128) {
        int j = i - 32768;
        int c = j >> 7, o = j & 127;
        g_Wg2T[j] = Wg[o*256 + 128 + c];
    }
}

// ---------------- double-buffered 64x64x16 SGEMM ----------------
template<int MA, int MB, bool SPLIT>
__global__ void gemm_db(const float* __restrict__ A, const float* __restrict__ B,
                        float* __restrict__ C, int M, int N, int K) {
    __shared__ float As[2][16][68];
    __shared__ float Bs[2][16][68];
    const int tid = threadIdx.x;
    const int m0 = blockIdx.x*64, n0 = blockIdx.y*64;
    int kb = 0, kn = K;
    if (SPLIT) { kn = K / gridDim.z; kb = blockIdx.z * kn; }
    const int nt = kn >> 4;
    const int tm = (tid>>4)<<2, tn = (tid&15)<<2;
    int a_r, a_c, b_r, b_c;
    if (MA==0) { a_r = tid>>2; a_c = (tid&3)<<2; }
    else       { a_r = tid>>4; a_c = (tid&15)<<2; }
    if (MB==0) { b_r = tid>>4; b_c = (tid&15)<<2; }
    else       { b_r = tid>>2; b_c = (tid&3)<<2; }
    float acc[4][4] = {};
    float ra[4], rb[4];
    auto LD = [&](int k0){
        float4 va, vb;
        if (MA==0) va = *(const float4*)&A[(size_t)(m0+a_r)*K + k0 + a_c];
        else       va = *(const float4*)&A[(size_t)(k0+a_r)*M + m0 + a_c];
        if (MB==0) vb = *(const float4*)&B[(size_t)(k0+b_r)*N + n0 + b_c];
        else       vb = *(const float4*)&B[(size_t)(n0+b_r)*K + k0 + b_c];
        ra[0]=va.x; ra[1]=va.y; ra[2]=va.z; ra[3]=va.w;
        rb[0]=vb.x; rb[1]=vb.y; rb[2]=vb.z; rb[3]=vb.w;
    };
    auto ST = [&](int buf){
        if (MA==0) {
            As[buf][a_c+0][a_r]=ra[0]; As[buf][a_c+1][a_r]=ra[1];
            As[buf][a_c+2][a_r]=ra[2]; As[buf][a_c+3][a_r]=ra[3];
        } else {
            *(float4*)&As[buf][a_r][a_c] = make_float4(ra[0],ra[1],ra[2],ra[3]);
        }
        if (MB==0) {
            *(float4*)&Bs[buf][b_r][b_c] = make_float4(rb[0],rb[1],rb[2],rb[3]);
        } else {
            Bs[buf][b_c+0][b_r]=rb[0]; Bs[buf][b_c+1][b_r]=rb[1];
            Bs[buf][b_c+2][b_r]=rb[2]; Bs[buf][b_c+3][b_r]=rb[3];
        }
    };
    LD(kb); ST(0); __syncthreads();
    for (int t = 0; t < nt; t++) {
        int cur = t & 1;
        if (t+1 < nt) LD(kb + ((t+1)<<4));
        #pragma unroll
        for (int kk = 0; kk < 16; kk++) {
            float4 a4 = *(const float4*)&As[cur][kk][tm];
            float4 b4 = *(const float4*)&Bs[cur][kk][tn];
            float av[4]={a4.x,a4.y,a4.z,a4.w}, bv[4]={b4.x,b4.y,b4.z,b4.w};
            #pragma unroll
            for (int i=0;i<4;i++)
                #pragma unroll
                for (int j=0;j<4;j++) acc[i][j] += av[i]*bv[j];
        }
        if (t+1 < nt) { ST(1-cur); __syncthreads(); }
    }
    float* dst = SPLIT ? (C + (size_t)blockIdx.z*M*N) : C;
    #pragma unroll
    for (int i=0;i<4;i++) {
        float4 v = make_float4(acc[i][0],acc[i][1],acc[i][2],acc[i][3]);
        *(float4*)&dst[(size_t)(m0+tm+i)*N + n0+tn] = v;
    }
}

// ---------------- reduce split-K partials (+optional bias over n) ----------------
__global__ void k_reduce(const float* __restrict__ P, const float* __restrict__ bias,
                         float* __restrict__ C, int MN, int N, int Z) {
    int i = blockIdx.x*256 + threadIdx.x;
    if (i >= MN) return;
    float s = 0.f;
    for (int z = 0; z < Z; z++) s += P[(size_t)z*MN + i];
    if (bias) s += bias[i % N];
    C[i] = s;
}

// ---------------- v1 = Wox2@box1 ; bef = Wo2@bo1 + bo2 ----------------
__global__ void k_bias1(const float* __restrict__ Wox2, const float* __restrict__ box1,
                        const float* __restrict__ Wo2, const float* __restrict__ bo1,
                        const float* __restrict__ bo2) {
    int wid = blockIdx.x*8 + (threadIdx.x>>5);
    int lane = threadIdx.x & 31;
    if (wid < 2048) {
        float s = 0.f;
        #pragma unroll
        for (int it=0; it<4; it++) {
            int k = (lane + 32*it) << 2;
            float4 w = *(const float4*)&Wox2[(size_t)wid*512 + k];
            float4 b = *(const float4*)&box1[k];
            s += w.x*b.x + w.y*b.y + w.z*b.z + w.w*b.w;
        }
        #pragma unroll
        for (int o=16;o;o>>=1) s += __shfl_down_sync(0xffffffffu, s, o);
        if (lane==0) g_v1[wid] = s;
    } else if (wid < 2176) {
        int o = wid - 2048;
        float s = 0.f;
        #pragma unroll
        for (int it=0; it<4; it++) {
            int k = (lane + 32*it) << 2;
            float4 w = *(const float4*)&Wo2[(size_t)o*512 + k];
            float4 b = *(const float4*)&bo1[k];
            s += w.x*b.x + w.y*b.y + w.z*b.z + w.w*b.w;
        }
        #pragma unroll
        for (int sh=16;sh;sh>>=1) s += __shfl_down_sync(0xffffffffu, s, sh);
        if (lane==0) g_bef[o] = bo2[o] + s;
    }
}

// ---------------- biasaug = bb + Wb@(v1+box2) ----------------
__global__ void k_bias2(const float* __restrict__ Wb, const float* __restrict__ box2,
                        const float* __restrict__ bb) {
    int o = blockIdx.x*8 + (threadIdx.x>>5);
    int lane = threadIdx.x & 31;
    float s = 0.f;
    #pragma unroll
    for (int it=0; it<16; it++) {
        int k = (lane + 32*it) << 2;
        float4 w  = *(const float4*)&Wb[(size_t)o*2048 + k];
        float4 v  = *(const float4*)&g_v1[k];
        float4 b2 = *(const float4*)&box2[k];
        s += w.x*(v.x+b2.x) + w.y*(v.y+b2.y) + w.z*(v.z+b2.z) + w.w*(v.w+b2.w);
    }
    #pragma unroll
    for (int sh=16;sh;sh>>=1) s += __shfl_down_sync(0xffffffffu, s, sh);
    if (lane==0) g_biasaug[o] = bb[o] + s;
}

// ---------------- spatial mean of x ----------------
__global__ void k_xp(const float* __restrict__ x) {
    int gw = (blockIdx.x * blockDim.x + threadIdx.x) >> 5;
    int lane = threadIdx.x & 31;
    const float* row = x + (size_t)gw * HWn;
    float v = (lane < HWn) ? row[lane] : 0.f;
    if (lane + 32 < HWn) v += row[lane + 32];
    #pragma unroll
    for (int o = 16; o; o >>= 1) v += __shfl_down_sync(0xffffffffu, v, o);
    if (lane == 0) g_xp[gw] = v * (1.0f/49.0f);
}

// ---------------- pre_output + softmax ----------------
__global__ void k_preout(const float* __restrict__ Wfc, float* __restrict__ out) {
    int b = blockIdx.x, t = threadIdx.x;
    __shared__ float f[BDn];
    __shared__ float lg[CLSn];
    __shared__ float mx, sm;
    f[t] = g_featp[b*BDn + t];
    __syncthreads();
    if (t < CLSn) {
        float acc = 0.f;
        const float* w = Wfc + t*BDn;
        for (int c = 0; c < BDn; c++) acc += w[c]*f[c];
        lg[t] = acc;
        out[OUT_PRE + b*CLSn + t] = acc;
    }
    __syncthreads();
    if (t == 0) { float m = -1e30f; for (int i = 0; i < CLSn; i++) m = fmaxf(m, lg[i]); mx = m; }
    __syncthreads();
    if (t < CLSn) lg[t] = expf(lg[t] - mx);
    __syncthreads();
    if (t == 0) { float s = 0.f; for (int i = 0; i < CLSn; i++) s += lg[i]; sm = s; }
    __syncthreads();
    if (t < CLSn) g_prescore[b*CLSn + t] = lg[t] / sm;
}

// ---------------- PageRank ----------------
__global__ void k_pagerank() {
    const int b = blockIdx.x, t = threadIdx.x;
    __shared__ float W[Mn*89];
    __shared__ float v0s[Mn], xA[Mn], xB[Mn];
    __shared__ float red[4];
    __shared__ float zx;
    for (int idx = t; idx < Mn*Mn; idx += 128)
        W[(idx/Mn)*89 + (idx%Mn)] = g_Wpr[idx];
    float vi = 0.f;
    if (t < Mn) {
        vi = (t >= Mn - CLSn) ? g_prescore[b*CLSn + (t - (Mn - CLSn))] : 0.f;
        v0s[t] = vi;
        xA[t] = vi * 87.f;
    }
    __syncthreads();
    const float s87 = vi * 87.f;
    const float coef = 0.15f / 87.f;
    for (int it = 0; it < 100; it++) {
        float* cur = (it & 1) ? xB : xA;
        float* nxt = (it & 1) ? xA : xB;
        float v = (t < Mn) ? cur[t] : 0.f;
        #pragma unroll
        for (int o = 16; o; o >>= 1) v += __shfl_down_sync(0xffffffffu, v, o);
        if ((t & 31) == 0) red[t >> 5] = v;
        __syncthreads();
        if (t == 0) zx = coef * (red[0] + red[1] + red[2] + red[3]);
        __syncthreads();
        if (t < Mn) {
            const float* wr = &W[t*89];
            float a0 = 0.f, a1 = 0.f, a2 = 0.f;
            #pragma unroll
            for (int j = 0; j < 84; j += 3) {
                a0 += wr[j]*cur[j]; a1 += wr[j+1]*cur[j+1]; a2 += wr[j+2]*cur[j+2];
            }
            a0 += wr[84]*cur[84]; a1 += wr[85]*cur[85]; a2 += wr[86]*cur[86];
            nxt[t] = (a0 + a1 + a2) + s87 * zx;
        }
        __syncthreads();
    }
    float xf = (t < Mn) ? xA[t] : 0.f;
    float v2 = xf*xf;
    #pragma unroll
    for (int o = 16; o; o >>= 1) v2 += __shfl_down_sync(0xffffffffu, v2, o);
    if ((t & 31) == 0) red[t >> 5] = v2;
    __syncthreads();
    if (t == 0) zx = sqrtf(red[0] + red[1] + red[2] + red[3]);
    __syncthreads();
    if (t < Mn) g_vy[b*Mn + t] = v0s[t] + xf / fmaxf(zx, 1e-12f);
}

// ---------------- conv: xl2[(b,p)][c] = (Wef @ x)[(b,p)][c] + bef[c] ----------------
__global__ void conv_xl_db(const float* __restrict__ x) {
    __shared__ float As[2][16][68];
    __shared__ float Bs[2][16][68];
    const int tid = threadIdx.x;
    const int m0 = blockIdx.x*64, n0 = blockIdx.y*64;
    const int tm = (tid>>4)<<2, tn = (tid&15)<<2;
    const int lm = tid & 63, lk0 = (tid>>6)<<2;
    const int m = m0 + lm;
    const float* xb = x + (size_t)(m/HWn)*(DOn*HWn) + (m%HWn);
    const int b_r = tid>>4, b_c = (tid&15)<<2;
    float acc[4][4] = {};
    float ra[4], rb[4];
    auto LD = [&](int k0){
        #pragma unroll
        for (int i=0;i<4;i++) ra[i] = xb[(size_t)(k0+lk0+i)*HWn];
        float4 vb = *(const float4*)&g_WefT[(size_t)(k0+b_r)*DLn + n0 + b_c];
        rb[0]=vb.x; rb[1]=vb.y; rb[2]=vb.z; rb[3]=vb.w;
    };
    auto ST = [&](int buf){
        #pragma unroll
        for (int i=0;i<4;i++) As[buf][lk0+i][lm]=ra[i];
        *(float4*)&Bs[buf][b_r][b_c] = make_float4(rb[0],rb[1],rb[2],rb[3]);
    };
    LD(0); ST(0); __syncthreads();
    const int nt = DOn/16;
    for (int t=0;t<nt;t++){
        int cur=t&1;
        if (t+1<nt) LD((t+1)<<4);
        #pragma unroll
        for (int kk=0;kk<16;kk++){
            float4 a4 = *(const float4*)&As[cur][kk][tm];
            float4 b4 = *(const float4*)&Bs[cur][kk][tn];
            float av[4]={a4.x,a4.y,a4.z,a4.w}, bv[4]={b4.x,b4.y,b4.z,b4.w};
            #pragma unroll
            for (int i=0;i<4;i++)
                #pragma unroll
                for (int j=0;j<4;j++) acc[i][j] += av[i]*bv[j];
        }
        if (t+1<nt){ ST(1-cur); __syncthreads(); }
    }
    float4 bf = *(const float4*)&g_bef[n0+tn];
    #pragma unroll
    for (int i=0;i<4;i++){
        float4 v = make_float4(acc[i][0]+bf.x, acc[i][1]+bf.y, acc[i][2]+bf.z, acc[i][3]+bf.w);
        *(float4*)&g_xl2[(size_t)(m0+tm+i)*DLn + n0+tn] = v;
    }
}

// ---------------- G_e = Wg[:,:128] @ (node_p * v_y_e) ----------------
__global__ void k_G(const float* __restrict__ node_p, const float* __restrict__ Wg) {
    int q = blockIdx.x;
    int o0 = blockIdx.y * 32;
    int t = threadIdx.x;
    __shared__ float Nq[128*88];
    for (int idx = t; idx < 128*Mn; idx += 256) {
        int k = idx / Mn, mm = idx % Mn;
        Nq[k*88 + mm] = node_p[idx] * g_vy[(128*q + k)*Mn + mm];
    }
    __syncthreads();
    for (int idx = t; idx < 32*Mn; idx += 256) {
        int o = o0 + idx / Mn, mm = idx % Mn;
        const float* w = Wg + o*256;
        float acc = 0.f;
        #pragma unroll 8
        for (int k = 0; k < 128; k++) acc += w[k] * Nq[k*88 + mm];
        g_G[q*NM + o*Mn + mm] = acc;
    }
}

// ---------------- fused chain: m1 -> g -> m2 -> softmax -> u (one block per batch) ----------------
// arena (floats): R0 [0,11264): m1s[c*88+m] then enS[m*88+n]
//                 R1 [11264,22748): aS[m*52+p](88 rows)+psS[c*52+p], then gsT[m*132+o]
//                 R2 [22748,34012): m2s[c*88+n]
//                 WG [34012,50396): WgS[c*128+o]
//                 MS [50396,50652): w(88), r(128)
#define C_R0 0
#define C_R1 11264
#define C_PS (C_R1 + 4576)
#define C_R2 22748
#define C_WG 34012
#define C_MS 50396
#define C_TOT 50652
#define CHAIN_SMEM (C_TOT*4)

__global__ void k_chain(const float* __restrict__ bg, const float* __restrict__ Ws,
                        const float* __restrict__ Wsp, const float* __restrict__ bsp) {
    extern __shared__ float S[];
    const int b = blockIdx.x, t = threadIdx.x, e = b & 1;
    float* m1s = S + C_R0;
    float* enS = S + C_R0;
    float* aS  = S + C_R1;
    float* psS = S + C_PS;
    float* gsT = S + C_R1;
    float* m2s = S + C_R2;
    float* WgS = S + C_WG;
    float* w   = S + C_MS;
    float* r   = S + C_MS + 88;
    __shared__ float mx, sm;

    const float* apsb = g_aps + (size_t)b*HWn;
    for (int i = t; i < Mn*HWn; i += 256) { int m=i/HWn, p=i%HWn; aS[m*52+p] = apsb[(size_t)m*NPIX + p]; }
    if (t < 52) aS[Mn*52 + t] = 0.f;
    for (int i = t; i < 128*HWn; i += 256) { int c=i/HWn, p=i%HWn; psS[c*52+p] = apsb[(size_t)(128+c)*NPIX + p]; }
    for (int i = t; i < 128*128/4; i += 256) ((float4*)WgS)[i] = ((const float4*)g_Wg2T)[i];
    __syncthreads();

    // stage2: m1[c][m] = relu(sum_p ps[c][p]*a[m][p]), 4 m's per unit
    for (int u = t; u < 128*22; u += 256) {
        int c = u/22, mb = (u%22)*4;
        float a0=0.f,a1=0.f,a2=0.f,a3=0.f;
        const float* pr = psS + c*52;
        const float* ar = aS + mb*52;
        #pragma unroll
        for (int p = 0; p < HWn; p++) {
            float pv = pr[p];
            a0 += pv*ar[p]; a1 += pv*ar[52+p]; a2 += pv*ar[104+p]; a3 += pv*ar[156+p];
        }
        float* d = m1s + c*88 + mb;
        d[0]=fmaxf(a0,0.f); d[1]=fmaxf(a1,0.f); d[2]=fmaxf(a2,0.f); d[3]=fmaxf(a3,0.f);
    }
    __syncthreads();

    // stage3: gsT[m][o] = G_e[o][m] + bg[o] + sum_c Wg2T[c][o]*m1[c][m], 4 o's per unit
    for (int u = t; u < Mn*32; u += 256) {
        int m = u%Mn, ob = (u/Mn)*4;
        float a0=0.f,a1=0.f,a2=0.f,a3=0.f;
        #pragma unroll 4
        for (int c = 0; c < 128; c++) {
            float mv = m1s[c*88+m];
            float4 wv = *(const float4*)&WgS[c*128+ob];
            a0 += wv.x*mv; a1 += wv.y*mv; a2 += wv.z*mv; a3 += wv.w*mv;
        }
        const float* Ge = g_G + e*NM;
        gsT[m*132+ob+0] = a0 + Ge[(ob+0)*Mn+m] + bg[ob+0];
        gsT[m*132+ob+1] = a1 + Ge[(ob+1)*Mn+m] + bg[ob+1];
        gsT[m*132+ob+2] = a2 + Ge[(ob+2)*Mn+m] + bg[ob+2];
        gsT[m*132+ob+3] = a3 + Ge[(ob+3)*Mn+m] + bg[ob+3];
    }
    __syncthreads();
    for (int i = t; i < Mn*Mn; i += 256) { int m=i/Mn, n=i%Mn; enS[m*88+n] = g_en[i]; }
    __syncthreads();

    // stage4: m2[c][n] = relu(sum_m g[c][m]*en[m][n]), 4 c's per unit
    for (int u = t; u < Mn*32; u += 256) {
        int n = u%Mn, cb = (u/Mn)*4;
        float a0=0.f,a1=0.f,a2=0.f,a3=0.f;
        #pragma unroll 4
        for (int m = 0; m < Mn; m++) {
            float ev = enS[m*88+n];
            float4 gv = *(const float4*)&gsT[m*132+cb];
            a0 += gv.x*ev; a1 += gv.y*ev; a2 += gv.z*ev; a3 += gv.w*ev;
        }
        m2s[(cb+0)*88+n]=fmaxf(a0,0.f);
        m2s[(cb+1)*88+n]=fmaxf(a1,0.f);
        m2s[(cb+2)*88+n]=fmaxf(a2,0.f);
        m2s[(cb+3)*88+n]=fmaxf(a3,0.f);
    }
    __syncthreads();

    // stage5: t_node -> softmax -> r -> u
    if (t < Mn) {
        float acc = 0.f;
        #pragma unroll 8
        for (int c = 0; c < 128; c++) acc += Ws[c] * m2s[c*88+t];
        w[t] = acc;
    }
    __syncthreads();
    if (t == 0) { float m = -1e30f; for (int i = 0; i < Mn; i++) m = fmaxf(m, w[i]); mx = m; }
    __syncthreads();
    if (t < Mn) w[t] = expf(w[t] - mx);
    __syncthreads();
    if (t == 0) { float s = 0.f; for (int i = 0; i < Mn; i++) s += w[i]; sm = s; }
    __syncthreads();
    if (t < Mn) w[t] /= sm;
    __syncthreads();
    if (t < 128) {
        float acc = 0.f;
        #pragma unroll
        for (int m = 0; m < Mn; m++) acc += m2s[t*88+m] * w[m];
        r[t] = acc;
    }
    __syncthreads();
    if (t < 128) {
        float acc = bsp[t];
        const float* wr = Wsp + t*128;
        #pragma unroll 8
        for (int c = 0; c < 128; c++) acc += wr[c] * r[c];
        g_u[b*128 + t] = fmaxf(acc, 0.f);
    }
}

// ---------------- head ----------------
__global__ void k_head(const float* __restrict__ Wfc2, float* __restrict__ out) {
    int b = blockIdx.x, t = threadIdx.x;
    __shared__ float us[128];
    __shared__ float feat[BDn];
    __shared__ float lg[CLSn];
    __shared__ float mx, sm;
    if (t < 128) us[t] = g_u[b*128 + t];
    __syncthreads();
    {
        float fp = g_featp[b*BDn + t];
        float acc = g_biasaug[t] + fp;
        const float* w = g_Wcomb + t*128;
        #pragma unroll 8
        for (int c = 0; c < 128; c++) acc += w[c] * us[c];
        feat[t] = acc;
        out[OUT_FEAT + b*BDn + t] = acc;
        out[OUT_FEATP + b*BDn + t] = fp;
    }
    __syncthreads();
    if (t < CLSn) {
        float acc = 0.f;
        const float* w = Wfc2 + t*BDn;
        #pragma unroll 8
        for (int c = 0; c < BDn; c++) acc += w[c] * feat[c];
        lg[t] = acc;
        out[OUT_OUT2 + b*CLSn + t] = acc;
    }
    __syncthreads();
    if (t == 0) { float m = -1e30f; for (int i = 0; i < CLSn; i++) m = fmaxf(m, lg[i]); mx = m; }
    __syncthreads();
    if (t < CLSn) lg[t] = expf(lg[t] - mx);
    __syncthreads();
    if (t == 0) { float s = 0.f; for (int i = 0; i < CLSn; i++) s += lg[i]; sm = s; }
    __syncthreads();
    if (t < CLSn) out[OUT_SOFT + b*CLSn + t] = lg[t] / sm;
}

extern "C" void kernel_launch(void* const* d_in, const int* in_sizes, int n_in,
                              void* d_out, int out_size) {
    const float* x     = (const float*)d_in[0];
    const float* Wb    = (const float*)d_in[1];
    const float* bb    = (const float*)d_in[2];
    const float* Wfc   = (const float*)d_in[3];
    const float* Wfc2  = (const float*)d_in[4];
    const float* Wo1   = (const float*)d_in[5];
    const float* bo1   = (const float*)d_in[6];
    const float* Wo2   = (const float*)d_in[7];
    const float* bo2   = (const float*)d_in[8];
    const float* Wa    = (const float*)d_in[9];
    const float* ba    = (const float*)d_in[10];
    const float* Wps   = (const float*)d_in[11];
    const float* bps   = (const float*)d_in[12];
    const float* node_p= (const float*)d_in[13];
    const float* Wg    = (const float*)d_in[14];
    const float* bg    = (const float*)d_in[15];
    const float* Wsp   = (const float*)d_in[16];
    const float* bsp   = (const float*)d_in[17];
    const float* Ws    = (const float*)d_in[18];
    const float* Wox1  = (const float*)d_in[20];
    const float* box1  = (const float*)d_in[21];
    const float* Wox2  = (const float*)d_in[22];
    const float* box2  = (const float*)d_in[23];
    const float* edge  = (const float*)d_in[24];
    float* out = (float*)d_out;

    float* pWefT  = nullptr; cudaGetSymbolAddress((void**)&pWefT,  g_WefT);
    float* pZ     = nullptr; cudaGetSymbolAddress((void**)&pZ,     g_Z);
    float* pWcomb = nullptr; cudaGetSymbolAddress((void**)&pWcomb, g_Wcomb);
    float* pPart  = nullptr; cudaGetSymbolAddress((void**)&pPart,  g_part);
    float* pXp    = nullptr; cudaGetSymbolAddress((void**)&pXp,    g_xp);
    float* pFeatp = nullptr; cudaGetSymbolAddress((void**)&pFeatp, g_featp);
    float* pWap   = nullptr; cudaGetSymbolAddress((void**)&pWap,   g_Wap);
    float* pXl2   = nullptr; cudaGetSymbolAddress((void**)&pXl2,   g_xl2);
    float* pAps   = nullptr; cudaGetSymbolAddress((void**)&pAps,   g_aps);

    static bool attr_done = false;
    if (!attr_done) {
        cudaFuncSetAttribute(k_chain, cudaFuncAttributeMaxDynamicSharedMemorySize, CHAIN_SMEM);
        attr_done = true;
    }

    k_prep_edge<<<1, 256>>>(edge);
    k_prep2<<<192, 256>>>(Wa, Wps, Wg);
    // WefT[c][o] = sum_j Wo1[j][c]*Wo2[o][j]  (M=2048, N=128, K=512) split x2
    gemm_db<1,1,true><<<dim3(32,2,2), 256>>>(Wo1, Wo2, pPart, 2048, 128, 512);
    k_reduce<<<1024, 256>>>(pPart, nullptr, pWefT, 2048*128, 128, 2);
    // Z = Wox2 @ Wox1  (2048 x 128, K=512) split x2
    gemm_db<0,0,true><<<dim3(32,2,2), 256>>>(Wox2, Wox1, pPart, 2048, 128, 512);
    k_reduce<<<1024, 256>>>(pPart, nullptr, pZ, 2048*128, 128, 2);
    // Wcomb = Wb @ Z  (256 x 128, K=2048) split x8
    gemm_db<0,0,true><<<dim3(4,2,8), 256>>>(Wb, pZ, pPart, 256, 128, 2048);
    k_reduce<<<128, 256>>>(pPart, nullptr, pWcomb, 256*128, 128, 8);
    k_bias1<<<272, 256>>>(Wox2, box1, Wo2, bo1, bo2);
    k_bias2<<<32, 256>>>(Wb, box2, bb);
    k_xp<<<65536, 256>>>(x);
    // featp = xp @ Wb^T + bb  (256 x 256, K=2048) split x8
    gemm_db<0,1,true><<<dim3(4,4,8), 256>>>(pXp, Wb, pPart, 256, 256, 2048);
    k_reduce<<<256, 256>>>(pPart, bb, pFeatp, 65536, 256, 8);
    k_preout<<<256, 256>>>(Wfc, out);
    k_pagerank<<<256, 128>>>();
    conv_xl_db<<<dim3(196,2), 256>>>(x);
    // aps = Wap @ xl2^T  (M=256, N=12544, K=128)
    gemm_db<0,1,false><<<dim3(4,196), 256>>>(pWap, pXl2, pAps, 256, NPIX, 128);
    k_G<<<dim3(2,4), 256>>>(node_p, Wg);
    k_chain<<<256, 256, CHAIN_SMEM>>>(bg, Ws, Wsp, bsp);
    k_head<<<256, 256>>>(Wfc2, out);
}

// round 12
// speedup vs baseline: 2.2177x; 1.0908x over previous
#include <cuda_runtime.h>

#define Bsz 256
#define Mn 87
#define CLSn 65
#define DLn 128
#define DOn 2048
#define BDn 256
#define HWn 49
#define NM (DLn*Mn)
#define NPIX (Bsz*HWn)

#define OUT_FEAT 0
#define OUT_OUT2 65536
#define OUT_SOFT 82176
#define OUT_PRE 98816
#define OUT_FEATP 115456

__device__ float g_xp[Bsz*DOn];
__device__ float g_featp[Bsz*BDn];
__device__ float g_prescore[Bsz*CLSn];
__device__ float g_vy[Bsz*Mn];
__device__ float g_Wpr[Mn*Mn];
__device__ float g_en[Mn*Mn];
__device__ float g_WefT[DOn*DLn];
__device__ float g_bef[DLn];
__device__ float g_Z[DOn*DLn];
__device__ float g_v1[DOn];
__device__ float g_Wcomb[BDn*DLn];
__device__ float g_biasaug[BDn];
__device__ float g_part[8*BDn*BDn];
__device__ float g_partB[8*BDn*DLn];
__device__ float g_xl2[NPIX*DLn];
__device__ float g_Wap[256*DLn];
__device__ float g_Wg2T[DLn*DLn];
__device__ float g_aps[256*NPIX];
__device__ float g_G[2*NM];
__device__ float g_u[Bsz*DLn];

// ---------------- edge prep ----------------
__global__ void k_prep_edge(const float* __restrict__ edge) {
    __shared__ float rs[Mn], di[Mn];
    int t = threadIdx.x;
    if (t < Mn) {
        float r = 0.f, c = 0.f;
        for (int j = 0; j < Mn; j++) { r += edge[t*Mn+j]; c += edge[j*Mn+t]; }
        rs[t] = r; di[t] = rsqrtf(c);
    }
    __syncthreads();
    for (int idx = t; idx < Mn*Mn; idx += blockDim.x) {
        int i = idx / Mn, j = idx % Mn;
        float e = edge[idx];
        g_Wpr[idx] = 0.85f * e / rs[j];
        g_en[idx]  = di[i] * e * di[j];
    }
}

// ---------------- Wap pad + Wg2 transpose ----------------
__global__ void k_prep2(const float* __restrict__ Wa, const float* __restrict__ Wps,
                        const float* __restrict__ Wg) {
    int i = blockIdx.x*256 + threadIdx.x;
    if (i < 256*128) {
        int m = i >> 7, c = i & 127;
        float v = 0.f;
        if (m < Mn) v = Wa[m*128 + c];
        else if (m >= 128) v = Wps[(m-128)*128 + c];
        g_Wap[i] = v;
    } else if (i < 256*128 + 128*128) {
        int j = i - 32768;
        int c = j >> 7, o = j & 127;
        g_Wg2T[j] = Wg[o*256 + 128 + c];
    }
}

// ---------------- double-buffered 64x64x16 SGEMM ----------------
template<int MA, int MB, bool SPLIT>
__global__ void gemm_db(const float* __restrict__ A, const float* __restrict__ B,
                        float* __restrict__ C, int M, int N, int K) {
    __shared__ float As[2][16][68];
    __shared__ float Bs[2][16][68];
    const int tid = threadIdx.x;
    const int m0 = blockIdx.x*64, n0 = blockIdx.y*64;
    int kb = 0, kn = K;
    if (SPLIT) { kn = K / gridDim.z; kb = blockIdx.z * kn; }
    const int nt = kn >> 4;
    const int tm = (tid>>4)<<2, tn = (tid&15)<<2;
    int a_r, a_c, b_r, b_c;
    if (MA==0) { a_r = tid>>2; a_c = (tid&3)<<2; }
    else       { a_r = tid>>4; a_c = (tid&15)<<2; }
    if (MB==0) { b_r = tid>>4; b_c = (tid&15)<<2; }
    else       { b_r = tid>>2; b_c = (tid&3)<<2; }
    float acc[4][4] = {};
    float ra[4], rb[4];
    auto LD = [&](int k0){
        float4 va, vb;
        if (MA==0) va = *(const float4*)&A[(size_t)(m0+a_r)*K + k0 + a_c];
        else       va = *(const float4*)&A[(size_t)(k0+a_r)*M + m0 + a_c];
        if (MB==0) vb = *(const float4*)&B[(size_t)(k0+b_r)*N + n0 + b_c];
        else       vb = *(const float4*)&B[(size_t)(n0+b_r)*K + k0 + b_c];
        ra[0]=va.x; ra[1]=va.y; ra[2]=va.z; ra[3]=va.w;
        rb[0]=vb.x; rb[1]=vb.y; rb[2]=vb.z; rb[3]=vb.w;
    };
    auto ST = [&](int buf){
        if (MA==0) {
            As[buf][a_c+0][a_r]=ra[0]; As[buf][a_c+1][a_r]=ra[1];
            As[buf][a_c+2][a_r]=ra[2]; As[buf][a_c+3][a_r]=ra[3];
        } else {
            *(float4*)&As[buf][a_r][a_c] = make_float4(ra[0],ra[1],ra[2],ra[3]);
        }
        if (MB==0) {
            *(float4*)&Bs[buf][b_r][b_c] = make_float4(rb[0],rb[1],rb[2],rb[3]);
        } else {
            Bs[buf][b_c+0][b_r]=rb[0]; Bs[buf][b_c+1][b_r]=rb[1];
            Bs[buf][b_c+2][b_r]=rb[2]; Bs[buf][b_c+3][b_r]=rb[3];
        }
    };
    LD(kb); ST(0); __syncthreads();
    for (int t = 0; t < nt; t++) {
        int cur = t & 1;
        if (t+1 < nt) LD(kb + ((t+1)<<4));
        #pragma unroll
        for (int kk = 0; kk < 16; kk++) {
            float4 a4 = *(const float4*)&As[cur][kk][tm];
            float4 b4 = *(const float4*)&Bs[cur][kk][tn];
            float av[4]={a4.x,a4.y,a4.z,a4.w}, bv[4]={b4.x,b4.y,b4.z,b4.w};
            #pragma unroll
            for (int i=0;i<4;i++)
                #pragma unroll
                for (int j=0;j<4;j++) acc[i][j] += av[i]*bv[j];
        }
        if (t+1 < nt) { ST(1-cur); __syncthreads(); }
    }
    float* dst = SPLIT ? (C + (size_t)blockIdx.z*M*N) : C;
    #pragma unroll
    for (int i=0;i<4;i++) {
        float4 v = make_float4(acc[i][0],acc[i][1],acc[i][2],acc[i][3]);
        *(float4*)&dst[(size_t)(m0+tm+i)*N + n0+tn] = v;
    }
}

// ---------------- reduce split-K partials (+optional bias over n) ----------------
__global__ void k_reduce(const float* __restrict__ P, const float* __restrict__ bias,
                         float* __restrict__ C, int MN, int N, int Z) {
    int i = blockIdx.x*256 + threadIdx.x;
    if (i >= MN) return;
    float s = 0.f;
    for (int z = 0; z < Z; z++) s += P[(size_t)z*MN + i];
    if (bias) s += bias[i % N];
    C[i] = s;
}

// ---------------- v1 = Wox2@box1 ; bef = Wo2@bo1 + bo2 ----------------
__global__ void k_bias1(const float* __restrict__ Wox2, const float* __restrict__ box1,
                        const float* __restrict__ Wo2, const float* __restrict__ bo1,
                        const float* __restrict__ bo2) {
    int wid = blockIdx.x*8 + (threadIdx.x>>5);
    int lane = threadIdx.x & 31;
    if (wid < 2048) {
        float s = 0.f;
        #pragma unroll
        for (int it=0; it<4; it++) {
            int k = (lane + 32*it) << 2;
            float4 w = *(const float4*)&Wox2[(size_t)wid*512 + k];
            float4 b = *(const float4*)&box1[k];
            s += w.x*b.x + w.y*b.y + w.z*b.z + w.w*b.w;
        }
        #pragma unroll
        for (int o=16;o;o>>=1) s += __shfl_down_sync(0xffffffffu, s, o);
        if (lane==0) g_v1[wid] = s;
    } else if (wid < 2176) {
        int o = wid - 2048;
        float s = 0.f;
        #pragma unroll
        for (int it=0; it<4; it++) {
            int k = (lane + 32*it) << 2;
            float4 w = *(const float4*)&Wo2[(size_t)o*512 + k];
            float4 b = *(const float4*)&bo1[k];
            s += w.x*b.x + w.y*b.y + w.z*b.z + w.w*b.w;
        }
        #pragma unroll
        for (int sh=16;sh;sh>>=1) s += __shfl_down_sync(0xffffffffu, s, sh);
        if (lane==0) g_bef[o] = bo2[o] + s;
    }
}

// ---------------- biasaug = bb + Wb@(v1+box2) ----------------
__global__ void k_bias2(const float* __restrict__ Wb, const float* __restrict__ box2,
                        const float* __restrict__ bb) {
    int o = blockIdx.x*8 + (threadIdx.x>>5);
    int lane = threadIdx.x & 31;
    float s = 0.f;
    #pragma unroll
    for (int it=0; it<16; it++) {
        int k = (lane + 32*it) << 2;
        float4 w  = *(const float4*)&Wb[(size_t)o*2048 + k];
        float4 v  = *(const float4*)&g_v1[k];
        float4 b2 = *(const float4*)&box2[k];
        s += w.x*(v.x+b2.x) + w.y*(v.y+b2.y) + w.z*(v.z+b2.z) + w.w*(v.w+b2.w);
    }
    #pragma unroll
    for (int sh=16;sh;sh>>=1) s += __shfl_down_sync(0xffffffffu, s, sh);
    if (lane==0) g_biasaug[o] = bb[o] + s;
}

// ---------------- spatial mean of x ----------------
__global__ void k_xp(const float* __restrict__ x) {
    int gw = (blockIdx.x * blockDim.x + threadIdx.x) >> 5;
    int lane = threadIdx.x & 31;
    const float* row = x + (size_t)gw * HWn;
    float v = (lane < HWn) ? row[lane] : 0.f;
    if (lane + 32 < HWn) v += row[lane + 32];
    #pragma unroll
    for (int o = 16; o; o >>= 1) v += __shfl_down_sync(0xffffffffu, v, o);
    if (lane == 0) g_xp[gw] = v * (1.0f/49.0f);
}

// ---------------- pre_output + softmax ----------------
__global__ void k_preout(const float* __restrict__ Wfc, float* __restrict__ out) {
    int b = blockIdx.x, t = threadIdx.x;
    __shared__ float f[BDn];
    __shared__ float lg[CLSn];
    __shared__ float mx, sm;
    f[t] = g_featp[b*BDn + t];
    __syncthreads();
    if (t < CLSn) {
        float acc = 0.f;
        const float* w = Wfc + t*BDn;
        for (int c = 0; c < BDn; c++) acc += w[c]*f[c];
        lg[t] = acc;
        out[OUT_PRE + b*CLSn + t] = acc;
    }
    __syncthreads();
    if (t == 0) { float m = -1e30f; for (int i = 0; i < CLSn; i++) m = fmaxf(m, lg[i]); mx = m; }
    __syncthreads();
    if (t < CLSn) lg[t] = expf(lg[t] - mx);
    __syncthreads();
    if (t == 0) { float s = 0.f; for (int i = 0; i < CLSn; i++) s += lg[i]; sm = s; }
    __syncthreads();
    if (t < CLSn) g_prescore[b*CLSn + t] = lg[t] / sm;
}

// ---------------- PageRank ----------------
__global__ void k_pagerank() {
    const int b = blockIdx.x, t = threadIdx.x;
    __shared__ float W[Mn*89];
    __shared__ float v0s[Mn], xA[Mn], xB[Mn];
    __shared__ float red[4];
    __shared__ float zx;
    for (int idx = t; idx < Mn*Mn; idx += 128)
        W[(idx/Mn)*89 + (idx%Mn)] = g_Wpr[idx];
    float vi = 0.f;
    if (t < Mn) {
        vi = (t >= Mn - CLSn) ? g_prescore[b*CLSn + (t - (Mn - CLSn))] : 0.f;
        v0s[t] = vi;
        xA[t] = vi * 87.f;
    }
    __syncthreads();
    const float s87 = vi * 87.f;
    const float coef = 0.15f / 87.f;
    for (int it = 0; it < 100; it++) {
        float* cur = (it & 1) ? xB : xA;
        float* nxt = (it & 1) ? xA : xB;
        float v = (t < Mn) ? cur[t] : 0.f;
        #pragma unroll
        for (int o = 16; o; o >>= 1) v += __shfl_down_sync(0xffffffffu, v, o);
        if ((t & 31) == 0) red[t >> 5] = v;
        __syncthreads();
        if (t == 0) zx = coef * (red[0] + red[1] + red[2] + red[3]);
        __syncthreads();
        if (t < Mn) {
            const float* wr = &W[t*89];
            float a0 = 0.f, a1 = 0.f, a2 = 0.f;
            #pragma unroll
            for (int j = 0; j < 84; j += 3) {
                a0 += wr[j]*cur[j]; a1 += wr[j+1]*cur[j+1]; a2 += wr[j+2]*cur[j+2];
            }
            a0 += wr[84]*cur[84]; a1 += wr[85]*cur[85]; a2 += wr[86]*cur[86];
            nxt[t] = (a0 + a1 + a2) + s87 * zx;
        }
        __syncthreads();
    }
    float xf = (t < Mn) ? xA[t] : 0.f;
    float v2 = xf*xf;
    #pragma unroll
    for (int o = 16; o; o >>= 1) v2 += __shfl_down_sync(0xffffffffu, v2, o);
    if ((t & 31) == 0) red[t >> 5] = v2;
    __syncthreads();
    if (t == 0) zx = sqrtf(red[0] + red[1] + red[2] + red[3]);
    __syncthreads();
    if (t < Mn) g_vy[b*Mn + t] = v0s[t] + xf / fmaxf(zx, 1e-12f);
}

// ---------------- conv: xl2[(b,p)][c] = (Wef @ x)[(b,p)][c] + bef[c] ----------------
__global__ void conv_xl_db(const float* __restrict__ x) {
    __shared__ float As[2][16][68];
    __shared__ float Bs[2][16][68];
    const int tid = threadIdx.x;
    const int m0 = blockIdx.x*64, n0 = blockIdx.y*64;
    const int tm = (tid>>4)<<2, tn = (tid&15)<<2;
    const int lm = tid & 63, lk0 = (tid>>6)<<2;
    const int m = m0 + lm;
    const float* xb = x + (size_t)(m/HWn)*(DOn*HWn) + (m%HWn);
    const int b_r = tid>>4, b_c = (tid&15)<<2;
    float acc[4][4] = {};
    float ra[4], rb[4];
    auto LD = [&](int k0){
        #pragma unroll
        for (int i=0;i<4;i++) ra[i] = xb[(size_t)(k0+lk0+i)*HWn];
        float4 vb = *(const float4*)&g_WefT[(size_t)(k0+b_r)*DLn + n0 + b_c];
        rb[0]=vb.x; rb[1]=vb.y; rb[2]=vb.z; rb[3]=vb.w;
    };
    auto ST = [&](int buf){
        #pragma unroll
        for (int i=0;i<4;i++) As[buf][lk0+i][lm]=ra[i];
        *(float4*)&Bs[buf][b_r][b_c] = make_float4(rb[0],rb[1],rb[2],rb[3]);
    };
    LD(0); ST(0); __syncthreads();
    const int nt = DOn/16;
    for (int t=0;t<nt;t++){
        int cur=t&1;
        if (t+1<nt) LD((t+1)<<4);
        #pragma unroll
        for (int kk=0;kk<16;kk++){
            float4 a4 = *(const float4*)&As[cur][kk][tm];
            float4 b4 = *(const float4*)&Bs[cur][kk][tn];
            float av[4]={a4.x,a4.y,a4.z,a4.w}, bv[4]={b4.x,b4.y,b4.z,b4.w};
            #pragma unroll
            for (int i=0;i<4;i++)
                #pragma unroll
                for (int j=0;j<4;j++) acc[i][j] += av[i]*bv[j];
        }
        if (t+1<nt){ ST(1-cur); __syncthreads(); }
    }
    float4 bf = *(const float4*)&g_bef[n0+tn];
    #pragma unroll
    for (int i=0;i<4;i++){
        float4 v = make_float4(acc[i][0]+bf.x, acc[i][1]+bf.y, acc[i][2]+bf.z, acc[i][3]+bf.w);
        *(float4*)&g_xl2[(size_t)(m0+tm+i)*DLn + n0+tn] = v;
    }
}

// ---------------- G_e = Wg[:,:128] @ (node_p * v_y_e) ----------------
__global__ void k_G(const float* __restrict__ node_p, const float* __restrict__ Wg) {
    int q = blockIdx.x;
    int o0 = blockIdx.y * 16;
    int t = threadIdx.x;
    __shared__ float Nq[128*88];
    for (int idx = t; idx < 128*Mn; idx += 256) {
        int k = idx / Mn, mm = idx % Mn;
        Nq[k*88 + mm] = node_p[idx] * g_vy[(128*q + k)*Mn + mm];
    }
    __syncthreads();
    for (int idx = t; idx < 16*Mn; idx += 256) {
        int o = o0 + idx / Mn, mm = idx % Mn;
        const float* w = Wg + o*256;
        float acc = 0.f;
        #pragma unroll 8
        for (int k = 0; k < 128; k++) acc += w[k] * Nq[k*88 + mm];
        g_G[q*NM + o*Mn + mm] = acc;
    }
}

// ---------------- fused chain: m1 -> g -> m2 -> softmax -> u (one block per batch) ----------------
#define C_R0 0
#define C_R1 11264
#define C_PS (C_R1 + 4576)
#define C_R2 22748
#define C_WG 34012
#define C_MS 50396
#define C_TOT 50652
#define CHAIN_SMEM (C_TOT*4)

__global__ void k_chain(const float* __restrict__ bg, const float* __restrict__ Ws,
                        const float* __restrict__ Wsp, const float* __restrict__ bsp) {
    extern __shared__ float S[];
    const int b = blockIdx.x, t = threadIdx.x, e = b & 1;
    float* m1s = S + C_R0;
    float* enS = S + C_R0;
    float* aS  = S + C_R1;
    float* psS = S + C_PS;
    float* gsT = S + C_R1;
    float* m2s = S + C_R2;
    float* WgS = S + C_WG;
    float* w   = S + C_MS;
    float* r   = S + C_MS + 88;
    __shared__ float mx, sm;

    const float* apsb = g_aps + (size_t)b*HWn;
    for (int i = t; i < Mn*HWn; i += 256) { int m=i/HWn, p=i%HWn; aS[m*52+p] = apsb[(size_t)m*NPIX + p]; }
    if (t < 52) aS[Mn*52 + t] = 0.f;
    for (int i = t; i < 128*HWn; i += 256) { int c=i/HWn, p=i%HWn; psS[c*52+p] = apsb[(size_t)(128+c)*NPIX + p]; }
    for (int i = t; i < 128*128/4; i += 256) ((float4*)WgS)[i] = ((const float4*)g_Wg2T)[i];
    __syncthreads();

    for (int u = t; u < 128*22; u += 256) {
        int c = u/22, mb = (u%22)*4;
        float a0=0.f,a1=0.f,a2=0.f,a3=0.f;
        const float* pr = psS + c*52;
        const float* ar = aS + mb*52;
        #pragma unroll
        for (int p = 0; p < HWn; p++) {
            float pv = pr[p];
            a0 += pv*ar[p]; a1 += pv*ar[52+p]; a2 += pv*ar[104+p]; a3 += pv*ar[156+p];
        }
        float* d = m1s + c*88 + mb;
        d[0]=fmaxf(a0,0.f); d[1]=fmaxf(a1,0.f); d[2]=fmaxf(a2,0.f); d[3]=fmaxf(a3,0.f);
    }
    __syncthreads();

    for (int u = t; u < Mn*32; u += 256) {
        int m = u%Mn, ob = (u/Mn)*4;
        float a0=0.f,a1=0.f,a2=0.f,a3=0.f;
        #pragma unroll 4
        for (int c = 0; c < 128; c++) {
            float mv = m1s[c*88+m];
            float4 wv = *(const float4*)&WgS[c*128+ob];
            a0 += wv.x*mv; a1 += wv.y*mv; a2 += wv.z*mv; a3 += wv.w*mv;
        }
        const float* Ge = g_G + e*NM;
        gsT[m*132+ob+0] = a0 + Ge[(ob+0)*Mn+m] + bg[ob+0];
        gsT[m*132+ob+1] = a1 + Ge[(ob+1)*Mn+m] + bg[ob+1];
        gsT[m*132+ob+2] = a2 + Ge[(ob+2)*Mn+m] + bg[ob+2];
        gsT[m*132+ob+3] = a3 + Ge[(ob+3)*Mn+m] + bg[ob+3];
    }
    __syncthreads();
    for (int i = t; i < Mn*Mn; i += 256) { int m=i/Mn, n=i%Mn; enS[m*88+n] = g_en[i]; }
    __syncthreads();

    for (int u = t; u < Mn*32; u += 256) {
        int n = u%Mn, cb = (u/Mn)*4;
        float a0=0.f,a1=0.f,a2=0.f,a3=0.f;
        #pragma unroll 4
        for (int m = 0; m < Mn; m++) {
            float ev = enS[m*88+n];
            float4 gv = *(const float4*)&gsT[m*132+cb];
            a0 += gv.x*ev; a1 += gv.y*ev; a2 += gv.z*ev; a3 += gv.w*ev;
        }
        m2s[(cb+0)*88+n]=fmaxf(a0,0.f);
        m2s[(cb+1)*88+n]=fmaxf(a1,0.f);
        m2s[(cb+2)*88+n]=fmaxf(a2,0.f);
        m2s[(cb+3)*88+n]=fmaxf(a3,0.f);
    }
    __syncthreads();

    if (t < Mn) {
        float acc = 0.f;
        #pragma unroll 8
        for (int c = 0; c < 128; c++) acc += Ws[c] * m2s[c*88+t];
        w[t] = acc;
    }
    __syncthreads();
    if (t == 0) { float m = -1e30f; for (int i = 0; i < Mn; i++) m = fmaxf(m, w[i]); mx = m; }
    __syncthreads();
    if (t < Mn) w[t] = expf(w[t] - mx);
    __syncthreads();
    if (t == 0) { float s = 0.f; for (int i = 0; i < Mn; i++) s += w[i]; sm = s; }
    __syncthreads();
    if (t < Mn) w[t] /= sm;
    __syncthreads();
    if (t < 128) {
        float acc = 0.f;
        #pragma unroll
        for (int m = 0; m < Mn; m++) acc += m2s[t*88+m] * w[m];
        r[t] = acc;
    }
    __syncthreads();
    if (t < 128) {
        float acc = bsp[t];
        const float* wr = Wsp + t*128;
        #pragma unroll 8
        for (int c = 0; c < 128; c++) acc += wr[c] * r[c];
        g_u[b*128 + t] = fmaxf(acc, 0.f);
    }
}

// ---------------- head ----------------
__global__ void k_head(const float* __restrict__ Wfc2, float* __restrict__ out) {
    int b = blockIdx.x, t = threadIdx.x;
    __shared__ float us[128];
    __shared__ float feat[BDn];
    __shared__ float lg[CLSn];
    __shared__ float mx, sm;
    if (t < 128) us[t] = g_u[b*128 + t];
    __syncthreads();
    {
        float fp = g_featp[b*BDn + t];
        float acc = g_biasaug[t] + fp;
        const float* w = g_Wcomb + t*128;
        #pragma unroll 8
        for (int c = 0; c < 128; c++) acc += w[c] * us[c];
        feat[t] = acc;
        out[OUT_FEAT + b*BDn + t] = acc;
        out[OUT_FEATP + b*BDn + t] = fp;
    }
    __syncthreads();
    if (t < CLSn) {
        float acc = 0.f;
        const float* w = Wfc2 + t*BDn;
        #pragma unroll 8
        for (int c = 0; c < BDn; c++) acc += w[c] * feat[c];
        lg[t] = acc;
        out[OUT_OUT2 + b*CLSn + t] = acc;
    }
    __syncthreads();
    if (t == 0) { float m = -1e30f; for (int i = 0; i < CLSn; i++) m = fmaxf(m, lg[i]); mx = m; }
    __syncthreads();
    if (t < CLSn) lg[t] = expf(lg[t] - mx);
    __syncthreads();
    if (t == 0) { float s = 0.f; for (int i = 0; i < CLSn; i++) s += lg[i]; sm = s; }
    __syncthreads();
    if (t < CLSn) out[OUT_SOFT + b*CLSn + t] = lg[t] / sm;
}

extern "C" void kernel_launch(void* const* d_in, const int* in_sizes, int n_in,
                              void* d_out, int out_size) {
    const float* x     = (const float*)d_in[0];
    const float* Wb    = (const float*)d_in[1];
    const float* bb    = (const float*)d_in[2];
    const float* Wfc   = (const float*)d_in[3];
    const float* Wfc2  = (const float*)d_in[4];
    const float* Wo1   = (const float*)d_in[5];
    const float* bo1   = (const float*)d_in[6];
    const float* Wo2   = (const float*)d_in[7];
    const float* bo2   = (const float*)d_in[8];
    const float* Wa    = (const float*)d_in[9];
    const float* ba    = (const float*)d_in[10];
    const float* Wps   = (const float*)d_in[11];
    const float* bps   = (const float*)d_in[12];
    const float* node_p= (const float*)d_in[13];
    const float* Wg    = (const float*)d_in[14];
    const float* bg    = (const float*)d_in[15];
    const float* Wsp   = (const float*)d_in[16];
    const float* bsp   = (const float*)d_in[17];
    const float* Ws    = (const float*)d_in[18];
    const float* Wox1  = (const float*)d_in[20];
    const float* box1  = (const float*)d_in[21];
    const float* Wox2  = (const float*)d_in[22];
    const float* box2  = (const float*)d_in[23];
    const float* edge  = (const float*)d_in[24];
    float* out = (float*)d_out;

    float* pWefT  = nullptr; cudaGetSymbolAddress((void**)&pWefT,  g_WefT);
    float* pZ     = nullptr; cudaGetSymbolAddress((void**)&pZ,     g_Z);
    float* pWcomb = nullptr; cudaGetSymbolAddress((void**)&pWcomb, g_Wcomb);
    float* pPart  = nullptr; cudaGetSymbolAddress((void**)&pPart,  g_part);
    float* pPartB = nullptr; cudaGetSymbolAddress((void**)&pPartB, g_partB);
    float* pXp    = nullptr; cudaGetSymbolAddress((void**)&pXp,    g_xp);
    float* pFeatp = nullptr; cudaGetSymbolAddress((void**)&pFeatp, g_featp);
    float* pWap   = nullptr; cudaGetSymbolAddress((void**)&pWap,   g_Wap);
    float* pXl2   = nullptr; cudaGetSymbolAddress((void**)&pXl2,   g_xl2);
    float* pAps   = nullptr; cudaGetSymbolAddress((void**)&pAps,   g_aps);

    static cudaStream_t sA = nullptr, sB = nullptr;
    static cudaEvent_t eRoot, eB1, eAps, eW2;
    if (!sA) {
        cudaFuncSetAttribute(k_chain, cudaFuncAttributeMaxDynamicSharedMemorySize, CHAIN_SMEM);
        cudaStreamCreateWithFlags(&sA, cudaStreamNonBlocking);
        cudaStreamCreateWithFlags(&sB, cudaStreamNonBlocking);
        cudaEventCreateWithFlags(&eRoot, cudaEventDisableTiming);
        cudaEventCreateWithFlags(&eB1,   cudaEventDisableTiming);
        cudaEventCreateWithFlags(&eAps,  cudaEventDisableTiming);
        cudaEventCreateWithFlags(&eW2,   cudaEventDisableTiming);
    }

    // root: tiny preps, then fork
    k_prep_edge<<<1, 256>>>(edge);
    k_prep2<<<192, 256>>>(Wa, Wps, Wg);
    cudaEventRecord(eRoot, 0);

    // ---- branch A: WefT -> bias1 -> conv -> aps ----
    cudaStreamWaitEvent(sA, eRoot, 0);
    gemm_db<1,1,false><<<dim3(32,2), 256, 0, sA>>>(Wo1, Wo2, pWefT, 2048, 128, 512);
    k_bias1<<<272, 256, 0, sA>>>(Wox2, box1, Wo2, bo1, bo2);
    cudaEventRecord(eB1, sA);
    conv_xl_db<<<dim3(196,2), 256, 0, sA>>>(x);
    gemm_db<0,1,false><<<dim3(4,196), 256, 0, sA>>>(pWap, pXl2, pAps, 256, NPIX, 128);
    cudaEventRecord(eAps, sA);

    // ---- branch B: Z -> Wcomb -> bias2 ----
    cudaStreamWaitEvent(sB, eRoot, 0);
    gemm_db<0,0,false><<<dim3(32,2), 256, 0, sB>>>(Wox2, Wox1, pZ, 2048, 128, 512);
    gemm_db<0,0,true><<<dim3(4,2,8), 256, 0, sB>>>(Wb, pZ, pPartB, 256, 128, 2048);
    k_reduce<<<128, 256, 0, sB>>>(pPartB, nullptr, pWcomb, 256*128, 128, 8);
    cudaStreamWaitEvent(sB, eB1, 0);
    k_bias2<<<32, 256, 0, sB>>>(Wb, box2, bb);
    cudaEventRecord(eW2, sB);

    // ---- root branch: xp -> featp -> preout -> pagerank -> G ----
    k_xp<<<65536, 256>>>(x);
    gemm_db<0,1,true><<<dim3(4,4,8), 256>>>(pXp, Wb, pPart, 256, 256, 2048);
    k_reduce<<<256, 256>>>(pPart, bb, pFeatp, 65536, 256, 8);
    k_preout<<<256, 256>>>(Wfc, out);
    k_pagerank<<<256, 128>>>();
    k_G<<<dim3(2,8), 256>>>(node_p, Wg);

    // join: chain needs aps (A) + G (root); head needs chain + Wcomb/biasaug (B)
    cudaStreamWaitEvent(0, eAps, 0);
    k_chain<<<256, 256, CHAIN_SMEM>>>(bg, Ws, Wsp, bsp);
    cudaStreamWaitEvent(0, eW2, 0);
    k_head<<<256, 256>>>(Wfc2, out);
}

// round 13
// speedup vs baseline: 2.3185x; 1.0455x over previous
#include <cuda_runtime.h>
#include <cuda_bf16.h>

#define Bsz 256
#define Mn 87
#define CLSn 65
#define DLn 128
#define DOn 2048
#define BDn 256
#define HWn 49
#define NM (DLn*Mn)
#define NPIX (Bsz*HWn)

#define OUT_FEAT 0
#define OUT_OUT2 65536
#define OUT_SOFT 82176
#define OUT_PRE 98816
#define OUT_FEATP 115456

__device__ float g_xp[Bsz*DOn];
__device__ float g_featp[Bsz*BDn];
__device__ float g_prescore[Bsz*CLSn];
__device__ float g_vy[Bsz*Mn];
__device__ float g_Wpr[Mn*Mn];
__device__ float g_en[Mn*Mn];
__device__ float g_WefT[DOn*DLn];
__device__ __nv_bfloat16 g_WhiT[DLn*DOn];
__device__ __nv_bfloat16 g_WloT[DLn*DOn];
__device__ float g_bef[DLn];
__device__ float g_Z[DOn*DLn];
__device__ float g_v1[DOn];
__device__ float g_Wcomb[BDn*DLn];
__device__ float g_biasaug[BDn];
__device__ float g_part[8*BDn*BDn];
__device__ float g_partB[8*BDn*DLn];
__device__ float g_xl2[NPIX*DLn];
__device__ float g_Wap[256*DLn];
__device__ float g_Wg2T[DLn*DLn];
__device__ float g_aps[256*NPIX];
__device__ float g_G[2*NM];
__device__ float g_u[Bsz*DLn];

#define MMA_BF16(d, a0,a1,a2,a3, b0,b1) \
  asm volatile("mma.sync.aligned.m16n8k16.row.col.f32.bf16.bf16.f32 " \
    "{%0,%1,%2,%3}, {%4,%5,%6,%7}, {%8,%9}, {%0,%1,%2,%3};" \
    : "+f"(d[0]),"+f"(d[1]),"+f"(d[2]),"+f"(d[3]) \
    : "r"(a0),"r"(a1),"r"(a2),"r"(a3),"r"(b0),"r"(b1))

// ---------------- edge prep ----------------
__global__ void k_prep_edge(const float* __restrict__ edge) {
    __shared__ float rs[Mn], di[Mn];
    int t = threadIdx.x;
    if (t < Mn) {
        float r = 0.f, c = 0.f;
        for (int j = 0; j < Mn; j++) { r += edge[t*Mn+j]; c += edge[j*Mn+t]; }
        rs[t] = r; di[t] = rsqrtf(c);
    }
    __syncthreads();
    for (int idx = t; idx < Mn*Mn; idx += blockDim.x) {
        int i = idx / Mn, j = idx % Mn;
        float e = edge[idx];
        g_Wpr[idx] = 0.85f * e / rs[j];
        g_en[idx]  = di[i] * e * di[j];
    }
}

// ---------------- Wap pad + Wg2 transpose ----------------
__global__ void k_prep2(const float* __restrict__ Wa, const float* __restrict__ Wps,
                        const float* __restrict__ Wg) {
    int i = blockIdx.x*256 + threadIdx.x;
    if (i < 256*128) {
        int m = i >> 7, c = i & 127;
        float v = 0.f;
        if (m < Mn) v = Wa[m*128 + c];
        else if (m >= 128) v = Wps[(m-128)*128 + c];
        g_Wap[i] = v;
    } else if (i < 256*128 + 128*128) {
        int j = i - 32768;
        int c = j >> 7, o = j & 127;
        g_Wg2T[j] = Wg[o*256 + 128 + c];
    }
}

// ---------------- split WefT[k][c] -> WhiT/WloT[c][k] (bf16) ----------------
__global__ void k_splitW() {
    int i = blockIdx.x*256 + threadIdx.x;   // 0..262143, i = c*2048 + k
    int c = i >> 11, k = i & 2047;
    float v = g_WefT[(size_t)k*DLn + c];
    __nv_bfloat16 h = __float2bfloat16(v);
    g_WhiT[i] = h;
    g_WloT[i] = __float2bfloat16(v - __bfloat162float(h));
}

// ---------------- double-buffered 64x64x16 SGEMM ----------------
template<int MA, int MB, bool SPLIT>
__global__ void gemm_db(const float* __restrict__ A, const float* __restrict__ B,
                        float* __restrict__ C, int M, int N, int K) {
    __shared__ float As[2][16][68];
    __shared__ float Bs[2][16][68];
    const int tid = threadIdx.x;
    const int m0 = blockIdx.x*64, n0 = blockIdx.y*64;
    int kb = 0, kn = K;
    if (SPLIT) { kn = K / gridDim.z; kb = blockIdx.z * kn; }
    const int nt = kn >> 4;
    const int tm = (tid>>4)<<2, tn = (tid&15)<<2;
    int a_r, a_c, b_r, b_c;
    if (MA==0) { a_r = tid>>2; a_c = (tid&3)<<2; }
    else       { a_r = tid>>4; a_c = (tid&15)<<2; }
    if (MB==0) { b_r = tid>>4; b_c = (tid&15)<<2; }
    else       { b_r = tid>>2; b_c = (tid&3)<<2; }
    float acc[4][4] = {};
    float ra[4], rb[4];
    auto LD = [&](int k0){
        float4 va, vb;
        if (MA==0) va = *(const float4*)&A[(size_t)(m0+a_r)*K + k0 + a_c];
        else       va = *(const float4*)&A[(size_t)(k0+a_r)*M + m0 + a_c];
        if (MB==0) vb = *(const float4*)&B[(size_t)(k0+b_r)*N + n0 + b_c];
        else       vb = *(const float4*)&B[(size_t)(n0+b_r)*K + k0 + b_c];
        ra[0]=va.x; ra[1]=va.y; ra[2]=va.z; ra[3]=va.w;
        rb[0]=vb.x; rb[1]=vb.y; rb[2]=vb.z; rb[3]=vb.w;
    };
    auto ST = [&](int buf){
        if (MA==0) {
            As[buf][a_c+0][a_r]=ra[0]; As[buf][a_c+1][a_r]=ra[1];
            As[buf][a_c+2][a_r]=ra[2]; As[buf][a_c+3][a_r]=ra[3];
        } else {
            *(float4*)&As[buf][a_r][a_c] = make_float4(ra[0],ra[1],ra[2],ra[3]);
        }
        if (MB==0) {
            *(float4*)&Bs[buf][b_r][b_c] = make_float4(rb[0],rb[1],rb[2],rb[3]);
        } else {
            Bs[buf][b_c+0][b_r]=rb[0]; Bs[buf][b_c+1][b_r]=rb[1];
            Bs[buf][b_c+2][b_r]=rb[2]; Bs[buf][b_c+3][b_r]=rb[3];
        }
    };
    LD(kb); ST(0); __syncthreads();
    for (int t = 0; t < nt; t++) {
        int cur = t & 1;
        if (t+1 < nt) LD(kb + ((t+1)<<4));
        #pragma unroll
        for (int kk = 0; kk < 16; kk++) {
            float4 a4 = *(const float4*)&As[cur][kk][tm];
            float4 b4 = *(const float4*)&Bs[cur][kk][tn];
            float av[4]={a4.x,a4.y,a4.z,a4.w}, bv[4]={b4.x,b4.y,b4.z,b4.w};
            #pragma unroll
            for (int i=0;i<4;i++)
                #pragma unroll
                for (int j=0;j<4;j++) acc[i][j] += av[i]*bv[j];
        }
        if (t+1 < nt) { ST(1-cur); __syncthreads(); }
    }
    float* dst = SPLIT ? (C + (size_t)blockIdx.z*M*N) : C;
    #pragma unroll
    for (int i=0;i<4;i++) {
        float4 v = make_float4(acc[i][0],acc[i][1],acc[i][2],acc[i][3]);
        *(float4*)&dst[(size_t)(m0+tm+i)*N + n0+tn] = v;
    }
}

// ---------------- reduce split-K partials ----------------
__global__ void k_reduce(const float* __restrict__ P, const float* __restrict__ bias,
                         float* __restrict__ C, int MN, int N, int Z) {
    int i = blockIdx.x*256 + threadIdx.x;
    if (i >= MN) return;
    float s = 0.f;
    for (int z = 0; z < Z; z++) s += P[(size_t)z*MN + i];
    if (bias) s += bias[i % N];
    C[i] = s;
}

// ---------------- v1 = Wox2@box1 ; bef = Wo2@bo1 + bo2 ----------------
__global__ void k_bias1(const float* __restrict__ Wox2, const float* __restrict__ box1,
                        const float* __restrict__ Wo2, const float* __restrict__ bo1,
                        const float* __restrict__ bo2) {
    int wid = blockIdx.x*8 + (threadIdx.x>>5);
    int lane = threadIdx.x & 31;
    if (wid < 2048) {
        float s = 0.f;
        #pragma unroll
        for (int it=0; it<4; it++) {
            int k = (lane + 32*it) << 2;
            float4 w = *(const float4*)&Wox2[(size_t)wid*512 + k];
            float4 b = *(const float4*)&box1[k];
            s += w.x*b.x + w.y*b.y + w.z*b.z + w.w*b.w;
        }
        #pragma unroll
        for (int o=16;o;o>>=1) s += __shfl_down_sync(0xffffffffu, s, o);
        if (lane==0) g_v1[wid] = s;
    } else if (wid < 2176) {
        int o = wid - 2048;
        float s = 0.f;
        #pragma unroll
        for (int it=0; it<4; it++) {
            int k = (lane + 32*it) << 2;
            float4 w = *(const float4*)&Wo2[(size_t)o*512 + k];
            float4 b = *(const float4*)&bo1[k];
            s += w.x*b.x + w.y*b.y + w.z*b.z + w.w*b.w;
        }
        #pragma unroll
        for (int sh=16;sh;sh>>=1) s += __shfl_down_sync(0xffffffffu, s, sh);
        if (lane==0) g_bef[o] = bo2[o] + s;
    }
}

// ---------------- biasaug = bb + Wb@(v1+box2) ----------------
__global__ void k_bias2(const float* __restrict__ Wb, const float* __restrict__ box2,
                        const float* __restrict__ bb) {
    int o = blockIdx.x*8 + (threadIdx.x>>5);
    int lane = threadIdx.x & 31;
    float s = 0.f;
    #pragma unroll
    for (int it=0; it<16; it++) {
        int k = (lane + 32*it) << 2;
        float4 w  = *(const float4*)&Wb[(size_t)o*2048 + k];
        float4 v  = *(const float4*)&g_v1[k];
        float4 b2 = *(const float4*)&box2[k];
        s += w.x*(v.x+b2.x) + w.y*(v.y+b2.y) + w.z*(v.z+b2.z) + w.w*(v.w+b2.w);
    }
    #pragma unroll
    for (int sh=16;sh;sh>>=1) s += __shfl_down_sync(0xffffffffu, s, sh);
    if (lane==0) g_biasaug[o] = bb[o] + s;
}

// ---------------- spatial mean of x ----------------
__global__ void k_xp(const float* __restrict__ x) {
    int gw = (blockIdx.x * blockDim.x + threadIdx.x) >> 5;
    int lane = threadIdx.x & 31;
    const float* row = x + (size_t)gw * HWn;
    float v = (lane < HWn) ? row[lane] : 0.f;
    if (lane + 32 < HWn) v += row[lane + 32];
    #pragma unroll
    for (int o = 16; o; o >>= 1) v += __shfl_down_sync(0xffffffffu, v, o);
    if (lane == 0) g_xp[gw] = v * (1.0f/49.0f);
}

// ---------------- pre_output + softmax ----------------
__global__ void k_preout(const float* __restrict__ Wfc, float* __restrict__ out) {
    int b = blockIdx.x, t = threadIdx.x;
    __shared__ float f[BDn];
    __shared__ float lg[CLSn];
    __shared__ float mx, sm;
    f[t] = g_featp[b*BDn + t];
    __syncthreads();
    if (t < CLSn) {
        float acc = 0.f;
        const float* w = Wfc + t*BDn;
        for (int c = 0; c < BDn; c++) acc += w[c]*f[c];
        lg[t] = acc;
        out[OUT_PRE + b*CLSn + t] = acc;
    }
    __syncthreads();
    if (t == 0) { float m = -1e30f; for (int i = 0; i < CLSn; i++) m = fmaxf(m, lg[i]); mx = m; }
    __syncthreads();
    if (t < CLSn) lg[t] = expf(lg[t] - mx);
    __syncthreads();
    if (t == 0) { float s = 0.f; for (int i = 0; i < CLSn; i++) s += lg[i]; sm = s; }
    __syncthreads();
    if (t < CLSn) g_prescore[b*CLSn + t] = lg[t] / sm;
}

// ---------------- PageRank ----------------
__global__ void k_pagerank() {
    const int b = blockIdx.x, t = threadIdx.x;
    __shared__ float W[Mn*89];
    __shared__ float v0s[Mn], xA[Mn], xB[Mn];
    __shared__ float red[4];
    __shared__ float zx;
    for (int idx = t; idx < Mn*Mn; idx += 128)
        W[(idx/Mn)*89 + (idx%Mn)] = g_Wpr[idx];
    float vi = 0.f;
    if (t < Mn) {
        vi = (t >= Mn - CLSn) ? g_prescore[b*CLSn + (t - (Mn - CLSn))] : 0.f;
        v0s[t] = vi;
        xA[t] = vi * 87.f;
    }
    __syncthreads();
    const float s87 = vi * 87.f;
    const float coef = 0.15f / 87.f;
    for (int it = 0; it < 100; it++) {
        float* cur = (it & 1) ? xB : xA;
        float* nxt = (it & 1) ? xA : xB;
        float v = (t < Mn) ? cur[t] : 0.f;
        #pragma unroll
        for (int o = 16; o; o >>= 1) v += __shfl_down_sync(0xffffffffu, v, o);
        if ((t & 31) == 0) red[t >> 5] = v;
        __syncthreads();
        if (t == 0) zx = coef * (red[0] + red[1] + red[2] + red[3]);
        __syncthreads();
        if (t < Mn) {
            const float* wr = &W[t*89];
            float a0 = 0.f, a1 = 0.f, a2 = 0.f;
            #pragma unroll
            for (int j = 0; j < 84; j += 3) {
                a0 += wr[j]*cur[j]; a1 += wr[j+1]*cur[j+1]; a2 += wr[j+2]*cur[j+2];
            }
            a0 += wr[84]*cur[84]; a1 += wr[85]*cur[85]; a2 += wr[86]*cur[86];
            nxt[t] = (a0 + a1 + a2) + s87 * zx;
        }
        __syncthreads();
    }
    float xf = (t < Mn) ? xA[t] : 0.f;
    float v2 = xf*xf;
    #pragma unroll
    for (int o = 16; o; o >>= 1) v2 += __shfl_down_sync(0xffffffffu, v2, o);
    if ((t & 31) == 0) red[t >> 5] = v2;
    __syncthreads();
    if (t == 0) zx = sqrtf(red[0] + red[1] + red[2] + red[3]);
    __syncthreads();
    if (t < Mn) g_vy[b*Mn + t] = v0s[t] + xf / fmaxf(zx, 1e-12f);
}

// ---------------- tensor-core conv: xl2 = x @ Wef^T + bef  (bf16-split HMMA) ----------------
// block tile: M=64 pixels, N=128 channels, K=16 per step, 128 steps.
// 8 warps: wm = warp&3 (16-row slice), wn = warp>>2 (64-col slice).
#define SA 24   // smem row stride in halfs (conflict-free: 12 words)
__global__ void __launch_bounds__(256) conv_xl_tc(const float* __restrict__ x) {
    __shared__ __nv_bfloat16 Ah[64*SA], Al[64*SA], Bh[128*SA], Bl[128*SA];
    const int tid = threadIdx.x;
    const int m0 = blockIdx.x*64;
    const int warp = tid>>5, lane = tid&31;
    const int wm = warp & 3, wn = warp >> 2;
    const int g = lane>>2, t4 = lane&3;
    const int arow = tid & 63, ak = (tid>>6)<<2;
    const int m = m0 + arow;
    const float* xb = x + (size_t)(m/HWn)*(DOn*HWn) + (m%HWn);
    const int brow = tid>>1, bk8 = (tid&1)<<3;
    const __nv_bfloat16* whp = g_WhiT + (size_t)brow*DOn + bk8;
    const __nv_bfloat16* wlp = g_WloT + (size_t)brow*DOn + bk8;
    float acc[8][4] = {};
    float rx[4]; uint4 rh, rl;
    auto LDG = [&](int k0){
        #pragma unroll
        for (int i=0;i<4;i++) rx[i] = xb[(size_t)(k0+ak+i)*HWn];
        rh = *(const uint4*)(whp + k0);
        rl = *(const uint4*)(wlp + k0);
    };
    auto STS = [&](){
        #pragma unroll
        for (int i=0;i<4;i++) {
            float v = rx[i];
            __nv_bfloat16 h = __float2bfloat16(v);
            Ah[arow*SA + ak + i] = h;
            Al[arow*SA + ak + i] = __float2bfloat16(v - __bfloat162float(h));
        }
        *(uint4*)&Bh[brow*SA + bk8] = rh;
        *(uint4*)&Bl[brow*SA + bk8] = rl;
    };
    LDG(0); STS(); __syncthreads();
    const int ar0 = (wm*16+g)*SA + t4*2;
    const int ar1 = (wm*16+g+8)*SA + t4*2;
    for (int ks = 0; ks < 128; ks++) {
        if (ks+1 < 128) LDG((ks+1)<<4);
        unsigned ah0 = *(const unsigned*)&Ah[ar0];
        unsigned ah1 = *(const unsigned*)&Ah[ar1];
        unsigned ah2 = *(const unsigned*)&Ah[ar0+8];
        unsigned ah3 = *(const unsigned*)&Ah[ar1+8];
        unsigned al0 = *(const unsigned*)&Al[ar0];
        unsigned al1 = *(const unsigned*)&Al[ar1];
        unsigned al2 = *(const unsigned*)&Al[ar0+8];
        unsigned al3 = *(const unsigned*)&Al[ar1+8];
        #pragma unroll
        for (int f = 0; f < 8; f++) {
            int col = (wn*64 + f*8 + g)*SA + t4*2;
            unsigned bh0 = *(const unsigned*)&Bh[col];
            unsigned bh1 = *(const unsigned*)&Bh[col+8];
            unsigned bl0 = *(const unsigned*)&Bl[col];
            unsigned bl1 = *(const unsigned*)&Bl[col+8];
            MMA_BF16(acc[f], ah0,ah1,ah2,ah3, bh0,bh1);
            MMA_BF16(acc[f], ah0,ah1,ah2,ah3, bl0,bl1);
            MMA_BF16(acc[f], al0,al1,al2,al3, bh0,bh1);
        }
        __syncthreads();
        if (ks+1 < 128) { STS(); __syncthreads(); }
    }
    const int mr = m0 + wm*16 + g;
    #pragma unroll
    for (int f = 0; f < 8; f++) {
        int cc = wn*64 + f*8 + t4*2;
        float2 bf = *(const float2*)&g_bef[cc];
        *(float2*)&g_xl2[(size_t)mr*DLn + cc]     = make_float2(acc[f][0]+bf.x, acc[f][1]+bf.y);
        *(float2*)&g_xl2[(size_t)(mr+8)*DLn + cc] = make_float2(acc[f][2]+bf.x, acc[f][3]+bf.y);
    }
}

// ---------------- G_e = Wg[:,:128] @ (node_p * v_y_e) ----------------
__global__ void k_G(const float* __restrict__ node_p, const float* __restrict__ Wg) {
    int q = blockIdx.x;
    int o0 = blockIdx.y * 16;
    int t = threadIdx.x;
    __shared__ float Nq[128*88];
    for (int idx = t; idx < 128*Mn; idx += 256) {
        int k = idx / Mn, mm = idx % Mn;
        Nq[k*88 + mm] = node_p[idx] * g_vy[(128*q + k)*Mn + mm];
    }
    __syncthreads();
    for (int idx = t; idx < 16*Mn; idx += 256) {
        int o = o0 + idx / Mn, mm = idx % Mn;
        const float* w = Wg + o*256;
        float acc = 0.f;
        #pragma unroll 8
        for (int k = 0; k < 128; k++) acc += w[k] * Nq[k*88 + mm];
        g_G[q*NM + o*Mn + mm] = acc;
    }
}

// ---------------- fused chain ----------------
#define C_R0 0
#define C_R1 11264
#define C_PS (C_R1 + 4576)
#define C_R2 22748
#define C_WG 34012
#define C_MS 50396
#define C_TOT 50652
#define CHAIN_SMEM (C_TOT*4)

__global__ void k_chain(const float* __restrict__ bg, const float* __restrict__ Ws,
                        const float* __restrict__ Wsp, const float* __restrict__ bsp) {
    extern __shared__ float S[];
    const int b = blockIdx.x, t = threadIdx.x, e = b & 1;
    float* m1s = S + C_R0;
    float* enS = S + C_R0;
    float* aS  = S + C_R1;
    float* psS = S + C_PS;
    float* gsT = S + C_R1;
    float* m2s = S + C_R2;
    float* WgS = S + C_WG;
    float* w   = S + C_MS;
    float* r   = S + C_MS + 88;
    __shared__ float mx, sm;

    const float* apsb = g_aps + (size_t)b*HWn;
    for (int i = t; i < Mn*HWn; i += 256) { int m=i/HWn, p=i%HWn; aS[m*52+p] = apsb[(size_t)m*NPIX + p]; }
    if (t < 52) aS[Mn*52 + t] = 0.f;
    for (int i = t; i < 128*HWn; i += 256) { int c=i/HWn, p=i%HWn; psS[c*52+p] = apsb[(size_t)(128+c)*NPIX + p]; }
    for (int i = t; i < 128*128/4; i += 256) ((float4*)WgS)[i] = ((const float4*)g_Wg2T)[i];
    __syncthreads();

    for (int u = t; u < 128*22; u += 256) {
        int c = u/22, mb = (u%22)*4;
        float a0=0.f,a1=0.f,a2=0.f,a3=0.f;
        const float* pr = psS + c*52;
        const float* ar = aS + mb*52;
        #pragma unroll
        for (int p = 0; p < HWn; p++) {
            float pv = pr[p];
            a0 += pv*ar[p]; a1 += pv*ar[52+p]; a2 += pv*ar[104+p]; a3 += pv*ar[156+p];
        }
        float* d = m1s + c*88 + mb;
        d[0]=fmaxf(a0,0.f); d[1]=fmaxf(a1,0.f); d[2]=fmaxf(a2,0.f); d[3]=fmaxf(a3,0.f);
    }
    __syncthreads();

    for (int u = t; u < Mn*32; u += 256) {
        int m = u%Mn, ob = (u/Mn)*4;
        float a0=0.f,a1=0.f,a2=0.f,a3=0.f;
        #pragma unroll 4
        for (int c = 0; c < 128; c++) {
            float mv = m1s[c*88+m];
            float4 wv = *(const float4*)&WgS[c*128+ob];
            a0 += wv.x*mv; a1 += wv.y*mv; a2 += wv.z*mv; a3 += wv.w*mv;
        }
        const float* Ge = g_G + e*NM;
        gsT[m*132+ob+0] = a0 + Ge[(ob+0)*Mn+m] + bg[ob+0];
        gsT[m*132+ob+1] = a1 + Ge[(ob+1)*Mn+m] + bg[ob+1];
        gsT[m*132+ob+2] = a2 + Ge[(ob+2)*Mn+m] + bg[ob+2];
        gsT[m*132+ob+3] = a3 + Ge[(ob+3)*Mn+m] + bg[ob+3];
    }
    __syncthreads();
    for (int i = t; i < Mn*Mn; i += 256) { int m=i/Mn, n=i%Mn; enS[m*88+n] = g_en[i]; }
    __syncthreads();

    for (int u = t; u < Mn*32; u += 256) {
        int n = u%Mn, cb = (u/Mn)*4;
        float a0=0.f,a1=0.f,a2=0.f,a3=0.f;
        #pragma unroll 4
        for (int m = 0; m < Mn; m++) {
            float ev = enS[m*88+n];
            float4 gv = *(const float4*)&gsT[m*132+cb];
            a0 += gv.x*ev; a1 += gv.y*ev; a2 += gv.z*ev; a3 += gv.w*ev;
        }
        m2s[(cb+0)*88+n]=fmaxf(a0,0.f);
        m2s[(cb+1)*88+n]=fmaxf(a1,0.f);
        m2s[(cb+2)*88+n]=fmaxf(a2,0.f);
        m2s[(cb+3)*88+n]=fmaxf(a3,0.f);
    }
    __syncthreads();

    if (t < Mn) {
        float acc = 0.f;
        #pragma unroll 8
        for (int c = 0; c < 128; c++) acc += Ws[c] * m2s[c*88+t];
        w[t] = acc;
    }
    __syncthreads();
    if (t == 0) { float m = -1e30f; for (int i = 0; i < Mn; i++) m = fmaxf(m, w[i]); mx = m; }
    __syncthreads();
    if (t < Mn) w[t] = expf(w[t] - mx);
    __syncthreads();
    if (t == 0) { float s = 0.f; for (int i = 0; i < Mn; i++) s += w[i]; sm = s; }
    __syncthreads();
    if (t < Mn) w[t] /= sm;
    __syncthreads();
    if (t < 128) {
        float acc = 0.f;
        #pragma unroll
        for (int m = 0; m < Mn; m++) acc += m2s[t*88+m] * w[m];
        r[t] = acc;
    }
    __syncthreads();
    if (t < 128) {
        float acc = bsp[t];
        const float* wr = Wsp + t*128;
        #pragma unroll 8
        for (int c = 0; c < 128; c++) acc += wr[c] * r[c];
        g_u[b*128 + t] = fmaxf(acc, 0.f);
    }
}

// ---------------- head ----------------
__global__ void k_head(const float* __restrict__ Wfc2, float* __restrict__ out) {
    int b = blockIdx.x, t = threadIdx.x;
    __shared__ float us[128];
    __shared__ float feat[BDn];
    __shared__ float lg[CLSn];
    __shared__ float mx, sm;
    if (t < 128) us[t] = g_u[b*128 + t];
    __syncthreads();
    {
        float fp = g_featp[b*BDn + t];
        float acc = g_biasaug[t] + fp;
        const float* w = g_Wcomb + t*128;
        #pragma unroll 8
        for (int c = 0; c < 128; c++) acc += w[c] * us[c];
        feat[t] = acc;
        out[OUT_FEAT + b*BDn + t] = acc;
        out[OUT_FEATP + b*BDn + t] = fp;
    }
    __syncthreads();
    if (t < CLSn) {
        float acc = 0.f;
        const float* w = Wfc2 + t*BDn;
        #pragma unroll 8
        for (int c = 0; c < BDn; c++) acc += w[c] * feat[c];
        lg[t] = acc;
        out[OUT_OUT2 + b*CLSn + t] = acc;
    }
    __syncthreads();
    if (t == 0) { float m = -1e30f; for (int i = 0; i < CLSn; i++) m = fmaxf(m, lg[i]); mx = m; }
    __syncthreads();
    if (t < CLSn) lg[t] = expf(lg[t] - mx);
    __syncthreads();
    if (t == 0) { float s = 0.f; for (int i = 0; i < CLSn; i++) s += lg[i]; sm = s; }
    __syncthreads();
    if (t < CLSn) out[OUT_SOFT + b*CLSn + t] = lg[t] / sm;
}

extern "C" void kernel_launch(void* const* d_in, const int* in_sizes, int n_in,
                              void* d_out, int out_size) {
    const float* x     = (const float*)d_in[0];
    const float* Wb    = (const float*)d_in[1];
    const float* bb    = (const float*)d_in[2];
    const float* Wfc   = (const float*)d_in[3];
    const float* Wfc2  = (const float*)d_in[4];
    const float* Wo1   = (const float*)d_in[5];
    const float* bo1   = (const float*)d_in[6];
    const float* Wo2   = (const float*)d_in[7];
    const float* bo2   = (const float*)d_in[8];
    const float* Wa    = (const float*)d_in[9];
    const float* ba    = (const float*)d_in[10];
    const float* Wps   = (const float*)d_in[11];
    const float* bps   = (const float*)d_in[12];
    const float* node_p= (const float*)d_in[13];
    const float* Wg    = (const float*)d_in[14];
    const float* bg    = (const float*)d_in[15];
    const float* Wsp   = (const float*)d_in[16];
    const float* bsp   = (const float*)d_in[17];
    const float* Ws    = (const float*)d_in[18];
    const float* Wox1  = (const float*)d_in[20];
    const float* box1  = (const float*)d_in[21];
    const float* Wox2  = (const float*)d_in[22];
    const float* box2  = (const float*)d_in[23];
    const float* edge  = (const float*)d_in[24];
    float* out = (float*)d_out;

    float* pWefT  = nullptr; cudaGetSymbolAddress((void**)&pWefT,  g_WefT);
    float* pZ     = nullptr; cudaGetSymbolAddress((void**)&pZ,     g_Z);
    float* pWcomb = nullptr; cudaGetSymbolAddress((void**)&pWcomb, g_Wcomb);
    float* pPart  = nullptr; cudaGetSymbolAddress((void**)&pPart,  g_part);
    float* pPartB = nullptr; cudaGetSymbolAddress((void**)&pPartB, g_partB);
    float* pXp    = nullptr; cudaGetSymbolAddress((void**)&pXp,    g_xp);
    float* pFeatp = nullptr; cudaGetSymbolAddress((void**)&pFeatp, g_featp);
    float* pWap   = nullptr; cudaGetSymbolAddress((void**)&pWap,   g_Wap);
    float* pXl2   = nullptr; cudaGetSymbolAddress((void**)&pXl2,   g_xl2);
    float* pAps   = nullptr; cudaGetSymbolAddress((void**)&pAps,   g_aps);

    static cudaStream_t sA = nullptr, sB = nullptr;
    static cudaEvent_t eRoot, eB1, eAps, eW2;
    if (!sA) {
        cudaFuncSetAttribute(k_chain, cudaFuncAttributeMaxDynamicSharedMemorySize, CHAIN_SMEM);
        cudaStreamCreateWithFlags(&sA, cudaStreamNonBlocking);
        cudaStreamCreateWithFlags(&sB, cudaStreamNonBlocking);
        cudaEventCreateWithFlags(&eRoot, cudaEventDisableTiming);
        cudaEventCreateWithFlags(&eB1,   cudaEventDisableTiming);
        cudaEventCreateWithFlags(&eAps,  cudaEventDisableTiming);
        cudaEventCreateWithFlags(&eW2,   cudaEventDisableTiming);
    }

    k_prep_edge<<<1, 256>>>(edge);
    k_prep2<<<192, 256>>>(Wa, Wps, Wg);
    cudaEventRecord(eRoot, 0);

    // ---- branch A: WefT -> split -> bias1 -> conv(TC) -> aps ----
    cudaStreamWaitEvent(sA, eRoot, 0);
    gemm_db<1,1,false><<<dim3(32,2), 256, 0, sA>>>(Wo1, Wo2, pWefT, 2048, 128, 512);
    k_splitW<<<1024, 256, 0, sA>>>();
    k_bias1<<<272, 256, 0, sA>>>(Wox2, box1, Wo2, bo1, bo2);
    cudaEventRecord(eB1, sA);
    conv_xl_tc<<<196, 256, 0, sA>>>(x);
    gemm_db<0,1,false><<<dim3(4,196), 256, 0, sA>>>(pWap, pXl2, pAps, 256, NPIX, 128);
    cudaEventRecord(eAps, sA);

    // ---- branch B: Z -> Wcomb -> bias2 ----
    cudaStreamWaitEvent(sB, eRoot, 0);
    gemm_db<0,0,false><<<dim3(32,2), 256, 0, sB>>>(Wox2, Wox1, pZ, 2048, 128, 512);
    gemm_db<0,0,true><<<dim3(4,2,8), 256, 0, sB>>>(Wb, pZ, pPartB, 256, 128, 2048);
    k_reduce<<<128, 256, 0, sB>>>(pPartB, nullptr, pWcomb, 256*128, 128, 8);
    cudaStreamWaitEvent(sB, eB1, 0);
    k_bias2<<<32, 256, 0, sB>>>(Wb, box2, bb);
    cudaEventRecord(eW2, sB);

    // ---- root: xp -> featp -> preout -> pagerank -> G ----
    k_xp<<<65536, 256>>>(x);
    gemm_db<0,1,true><<<dim3(4,4,8), 256>>>(pXp, Wb, pPart, 256, 256, 2048);
    k_reduce<<<256, 256>>>(pPart, bb, pFeatp, 65536, 256, 8);
    k_preout<<<256, 256>>>(Wfc, out);
    k_pagerank<<<256, 128>>>();
    k_G<<<dim3(2,8), 256>>>(node_p, Wg);

    cudaStreamWaitEvent(0, eAps, 0);
    k_chain<<<256, 256, CHAIN_SMEM>>>(bg, Ws, Wsp, bsp);
    cudaStreamWaitEvent(0, eW2, 0);
    k_head<<<256, 256>>>(Wfc2, out);
}

// round 15
// speedup vs baseline: 2.3724x; 1.0233x over previous
#include <cuda_runtime.h>
#include <cuda_bf16.h>

#define Bsz 256
#define Mn 87
#define CLSn 65
#define DLn 128
#define DOn 2048
#define BDn 256
#define HWn 49
#define NM (DLn*Mn)
#define NPIX (Bsz*HWn)

#define OUT_FEAT 0
#define OUT_OUT2 65536
#define OUT_SOFT 82176
#define OUT_PRE 98816
#define OUT_FEATP 115456

__device__ float g_xp[Bsz*DOn];
__device__ float g_featp[Bsz*BDn];
__device__ float g_prescore[Bsz*CLSn];
__device__ float g_vy[Bsz*Mn];
__device__ float g_Wpr[Mn*Mn];
__device__ float g_en[Mn*Mn];
__device__ __nv_bfloat16 g_WhiT[DLn*DOn];
__device__ __nv_bfloat16 g_WloT[DLn*DOn];
__device__ float g_bef[DLn];
__device__ float g_Z[DOn*DLn];
__device__ float g_v1[DOn];
__device__ float g_Wcomb[BDn*DLn];
__device__ float g_biasaug[BDn];
__device__ float g_part[8*BDn*BDn];
__device__ float g_partB[8*BDn*DLn];
__device__ float g_xl2[NPIX*DLn];
__device__ float g_Wap[256*DLn];
__device__ float g_Wg2T[DLn*DLn];
__device__ float g_aps[256*NPIX];
__device__ float g_G[2*NM];
__device__ float g_u[Bsz*DLn];

#define MMA_BF16(d, a0,a1,a2,a3, b0,b1) \
  asm volatile("mma.sync.aligned.m16n8k16.row.col.f32.bf16.bf16.f32 " \
    "{%0,%1,%2,%3}, {%4,%5,%6,%7}, {%8,%9}, {%0,%1,%2,%3};" \
    : "+f"(d[0]),"+f"(d[1]),"+f"(d[2]),"+f"(d[3]) \
    : "r"(a0),"r"(a1),"r"(a2),"r"(a3),"r"(b0),"r"(b1))

// ---------------- edge prep ----------------
__global__ void k_prep_edge(const float* __restrict__ edge) {
    __shared__ float rs[Mn], di[Mn];
    int t = threadIdx.x;
    if (t < Mn) {
        float r = 0.f, c = 0.f;
        for (int j = 0; j < Mn; j++) { r += edge[t*Mn+j]; c += edge[j*Mn+t]; }
        rs[t] = r; di[t] = rsqrtf(c);
    }
    __syncthreads();
    for (int idx = t; idx < Mn*Mn; idx += blockDim.x) {
        int i = idx / Mn, j = idx % Mn;
        float e = edge[idx];
        g_Wpr[idx] = 0.85f * e / rs[j];
        g_en[idx]  = di[i] * e * di[j];
    }
}

// ---------------- Wap pad + Wg2 transpose ----------------
__global__ void k_prep2(const float* __restrict__ Wa, const float* __restrict__ Wps,
                        const float* __restrict__ Wg) {
    int i = blockIdx.x*256 + threadIdx.x;
    if (i < 256*128) {
        int m = i >> 7, c = i & 127;
        float v = 0.f;
        if (m < Mn) v = Wa[m*128 + c];
        else if (m >= 128) v = Wps[(m-128)*128 + c];
        g_Wap[i] = v;
    } else if (i < 256*128 + 128*128) {
        int j = i - 32768;
        int c = j >> 7, o = j & 127;
        g_Wg2T[j] = Wg[o*256 + 128 + c];
    }
}

// ---------------- WefT GEMM with fused bf16 split epilogue ----------------
__global__ void gemm_wef_split(const float* __restrict__ Wo1, const float* __restrict__ Wo2) {
    __shared__ float As[2][16][68];
    __shared__ float Bs[2][16][68];
    const int tid = threadIdx.x;
    const int m0 = blockIdx.x*64, n0 = blockIdx.y*64;   // m: 2048 (k), n: 128 (c)
    const int tm = (tid>>4)<<2, tn = (tid&15)<<2;
    const int a_r = tid>>4, a_c = (tid&15)<<2;
    const int b_r = tid>>2, b_c = (tid&3)<<2;
    float acc[4][4] = {};
    float ra[4], rb[4];
    auto LD = [&](int k0){
        float4 va = *(const float4*)&Wo1[(size_t)(k0+a_r)*2048 + m0 + a_c];
        float4 vb = *(const float4*)&Wo2[(size_t)(n0+b_r)*512 + k0 + b_c];
        ra[0]=va.x; ra[1]=va.y; ra[2]=va.z; ra[3]=va.w;
        rb[0]=vb.x; rb[1]=vb.y; rb[2]=vb.z; rb[3]=vb.w;
    };
    auto ST = [&](int buf){
        *(float4*)&As[buf][a_r][a_c] = make_float4(ra[0],ra[1],ra[2],ra[3]);
        Bs[buf][b_c+0][b_r]=rb[0]; Bs[buf][b_c+1][b_r]=rb[1];
        Bs[buf][b_c+2][b_r]=rb[2]; Bs[buf][b_c+3][b_r]=rb[3];
    };
    LD(0); ST(0); __syncthreads();
    for (int t = 0; t < 32; t++) {
        int cur = t & 1;
        if (t+1 < 32) LD((t+1)<<4);
        #pragma unroll
        for (int kk = 0; kk < 16; kk++) {
            float4 a4 = *(const float4*)&As[cur][kk][tm];
            float4 b4 = *(const float4*)&Bs[cur][kk][tn];
            float av[4]={a4.x,a4.y,a4.z,a4.w}, bv[4]={b4.x,b4.y,b4.z,b4.w};
            #pragma unroll
            for (int i=0;i<4;i++)
                #pragma unroll
                for (int j=0;j<4;j++) acc[i][j] += av[i]*bv[j];
        }
        if (t+1 < 32) { ST(1-cur); __syncthreads(); }
    }
    #pragma unroll
    for (int i=0;i<4;i++) {
        int k = m0+tm+i;
        #pragma unroll
        for (int j=0;j<4;j++) {
            int c = n0+tn+j;
            float v = acc[i][j];
            __nv_bfloat16 h = __float2bfloat16(v);
            g_WhiT[(size_t)c*DOn + k] = h;
            g_WloT[(size_t)c*DOn + k] = __float2bfloat16(v - __bfloat162float(h));
        }
    }
}

// ---------------- double-buffered 64x64x16 SGEMM ----------------
template<int MA, int MB, bool SPLIT>
__global__ void gemm_db(const float* __restrict__ A, const float* __restrict__ B,
                        float* __restrict__ C, int M, int N, int K) {
    __shared__ float As[2][16][68];
    __shared__ float Bs[2][16][68];
    const int tid = threadIdx.x;
    const int m0 = blockIdx.x*64, n0 = blockIdx.y*64;
    int kb = 0, kn = K;
    if (SPLIT) { kn = K / gridDim.z; kb = blockIdx.z * kn; }
    const int nt = kn >> 4;
    const int tm = (tid>>4)<<2, tn = (tid&15)<<2;
    int a_r, a_c, b_r, b_c;
    if (MA==0) { a_r = tid>>2; a_c = (tid&3)<<2; }
    else       { a_r = tid>>4; a_c = (tid&15)<<2; }
    if (MB==0) { b_r = tid>>4; b_c = (tid&15)<<2; }
    else       { b_r = tid>>2; b_c = (tid&3)<<2; }
    float acc[4][4] = {};
    float ra[4], rb[4];
    auto LD = [&](int k0){
        float4 va, vb;
        if (MA==0) va = *(const float4*)&A[(size_t)(m0+a_r)*K + k0 + a_c];
        else       va = *(const float4*)&A[(size_t)(k0+a_r)*M + m0 + a_c];
        if (MB==0) vb = *(const float4*)&B[(size_t)(k0+b_r)*N + n0 + b_c];
        else       vb = *(const float4*)&B[(size_t)(n0+b_r)*K + k0 + b_c];
        ra[0]=va.x; ra[1]=va.y; ra[2]=va.z; ra[3]=va.w;
        rb[0]=vb.x; rb[1]=vb.y; rb[2]=vb.z; rb[3]=vb.w;
    };
    auto ST = [&](int buf){
        if (MA==0) {
            As[buf][a_c+0][a_r]=ra[0]; As[buf][a_c+1][a_r]=ra[1];
            As[buf][a_c+2][a_r]=ra[2]; As[buf][a_c+3][a_r]=ra[3];
        } else {
            *(float4*)&As[buf][a_r][a_c] = make_float4(ra[0],ra[1],ra[2],ra[3]);
        }
        if (MB==0) {
            *(float4*)&Bs[buf][b_r][b_c] = make_float4(rb[0],rb[1],rb[2],rb[3]);
        } else {
            Bs[buf][b_c+0][b_r]=rb[0]; Bs[buf][b_c+1][b_r]=rb[1];
            Bs[buf][b_c+2][b_r]=rb[2]; Bs[buf][b_c+3][b_r]=rb[3];
        }
    };
    LD(kb); ST(0); __syncthreads();
    for (int t = 0; t < nt; t++) {
        int cur = t & 1;
        if (t+1 < nt) LD(kb + ((t+1)<<4));
        #pragma unroll
        for (int kk = 0; kk < 16; kk++) {
            float4 a4 = *(const float4*)&As[cur][kk][tm];
            float4 b4 = *(const float4*)&Bs[cur][kk][tn];
            float av[4]={a4.x,a4.y,a4.z,a4.w}, bv[4]={b4.x,b4.y,b4.z,b4.w};
            #pragma unroll
            for (int i=0;i<4;i++)
                #pragma unroll
                for (int j=0;j<4;j++) acc[i][j] += av[i]*bv[j];
        }
        if (t+1 < nt) { ST(1-cur); __syncthreads(); }
    }
    float* dst = SPLIT ? (C + (size_t)blockIdx.z*M*N) : C;
    #pragma unroll
    for (int i=0;i<4;i++) {
        float4 v = make_float4(acc[i][0],acc[i][1],acc[i][2],acc[i][3]);
        *(float4*)&dst[(size_t)(m0+tm+i)*N + n0+tn] = v;
    }
}

// ---------------- reduce split-K partials ----------------
__global__ void k_reduce(const float* __restrict__ P, const float* __restrict__ bias,
                         float* __restrict__ C, int MN, int N, int Z) {
    int i = blockIdx.x*256 + threadIdx.x;
    if (i >= MN) return;
    float s = 0.f;
    for (int z = 0; z < Z; z++) s += P[(size_t)z*MN + i];
    if (bias) s += bias[i % N];
    C[i] = s;
}

// ---------------- v1 = Wox2@box1 ; bef = Wo2@bo1 + bo2 ----------------
__global__ void k_bias1(const float* __restrict__ Wox2, const float* __restrict__ box1,
                        const float* __restrict__ Wo2, const float* __restrict__ bo1,
                        const float* __restrict__ bo2) {
    int wid = blockIdx.x*8 + (threadIdx.x>>5);
    int lane = threadIdx.x & 31;
    if (wid < 2048) {
        float s = 0.f;
        #pragma unroll
        for (int it=0; it<4; it++) {
            int k = (lane + 32*it) << 2;
            float4 w = *(const float4*)&Wox2[(size_t)wid*512 + k];
            float4 b = *(const float4*)&box1[k];
            s += w.x*b.x + w.y*b.y + w.z*b.z + w.w*b.w;
        }
        #pragma unroll
        for (int o=16;o;o>>=1) s += __shfl_down_sync(0xffffffffu, s, o);
        if (lane==0) g_v1[wid] = s;
    } else if (wid < 2176) {
        int o = wid - 2048;
        float s = 0.f;
        #pragma unroll
        for (int it=0; it<4; it++) {
            int k = (lane + 32*it) << 2;
            float4 w = *(const float4*)&Wo2[(size_t)o*512 + k];
            float4 b = *(const float4*)&bo1[k];
            s += w.x*b.x + w.y*b.y + w.z*b.z + w.w*b.w;
        }
        #pragma unroll
        for (int sh=16;sh;sh>>=1) s += __shfl_down_sync(0xffffffffu, s, sh);
        if (lane==0) g_bef[o] = bo2[o] + s;
    }
}

// ---------------- biasaug = bb + Wb@(v1+box2) ----------------
__global__ void k_bias2(const float* __restrict__ Wb, const float* __restrict__ box2,
                        const float* __restrict__ bb) {
    int o = blockIdx.x*8 + (threadIdx.x>>5);
    int lane = threadIdx.x & 31;
    float s = 0.f;
    #pragma unroll
    for (int it=0; it<16; it++) {
        int k = (lane + 32*it) << 2;
        float4 w  = *(const float4*)&Wb[(size_t)o*2048 + k];
        float4 v  = *(const float4*)&g_v1[k];
        float4 b2 = *(const float4*)&box2[k];
        s += w.x*(v.x+b2.x) + w.y*(v.y+b2.y) + w.z*(v.z+b2.z) + w.w*(v.w+b2.w);
    }
    #pragma unroll
    for (int sh=16;sh;sh>>=1) s += __shfl_down_sync(0xffffffffu, s, sh);
    if (lane==0) g_biasaug[o] = bb[o] + s;
}

// ---------------- spatial mean of x ----------------
__global__ void k_xp(const float* __restrict__ x) {
    int gw = (blockIdx.x * blockDim.x + threadIdx.x) >> 5;
    int lane = threadIdx.x & 31;
    const float* row = x + (size_t)gw * HWn;
    float v = (lane < HWn) ? row[lane] : 0.f;
    if (lane + 32 < HWn) v += row[lane + 32];
    #pragma unroll
    for (int o = 16; o; o >>= 1) v += __shfl_down_sync(0xffffffffu, v, o);
    if (lane == 0) g_xp[gw] = v * (1.0f/49.0f);
}

// ---------------- featp reduce + pre_output + softmax (fused) ----------------
__global__ void k_preout(const float* __restrict__ Wfc, const float* __restrict__ bb,
                         float* __restrict__ out) {
    int b = blockIdx.x, t = threadIdx.x;
    __shared__ float f[BDn];
    __shared__ float lg[CLSn];
    __shared__ float mx, sm;
    {
        float s = bb[t];
        #pragma unroll
        for (int z = 0; z < 8; z++) s += g_part[(size_t)z*65536 + b*BDn + t];
        f[t] = s;
        g_featp[b*BDn + t] = s;
    }
    __syncthreads();
    if (t < CLSn) {
        float acc = 0.f;
        const float* w = Wfc + t*BDn;
        for (int c = 0; c < BDn; c++) acc += w[c]*f[c];
        lg[t] = acc;
        out[OUT_PRE + b*CLSn + t] = acc;
    }
    __syncthreads();
    if (t == 0) { float m = -1e30f; for (int i = 0; i < CLSn; i++) m = fmaxf(m, lg[i]); mx = m; }
    __syncthreads();
    if (t < CLSn) lg[t] = expf(lg[t] - mx);
    __syncthreads();
    if (t == 0) { float s = 0.f; for (int i = 0; i < CLSn; i++) s += lg[i]; sm = s; }
    __syncthreads();
    if (t < CLSn) g_prescore[b*CLSn + t] = lg[t] / sm;
}

// ---------------- PageRank ----------------
__global__ void k_pagerank() {
    const int b = blockIdx.x, t = threadIdx.x;
    __shared__ float W[Mn*89];
    __shared__ float v0s[Mn], xA[Mn], xB[Mn];
    __shared__ float red[4];
    __shared__ float zx;
    for (int idx = t; idx < Mn*Mn; idx += 128)
        W[(idx/Mn)*89 + (idx%Mn)] = g_Wpr[idx];
    float vi = 0.f;
    if (t < Mn) {
        vi = (t >= Mn - CLSn) ? g_prescore[b*CLSn + (t - (Mn - CLSn))] : 0.f;
        v0s[t] = vi;
        xA[t] = vi * 87.f;
    }
    __syncthreads();
    const float s87 = vi * 87.f;
    const float coef = 0.15f / 87.f;
    for (int it = 0; it < 100; it++) {
        float* cur = (it & 1) ? xB : xA;
        float* nxt = (it & 1) ? xA : xB;
        float v = (t < Mn) ? cur[t] : 0.f;
        #pragma unroll
        for (int o = 16; o; o >>= 1) v += __shfl_down_sync(0xffffffffu, v, o);
        if ((t & 31) == 0) red[t >> 5] = v;
        __syncthreads();
        if (t == 0) zx = coef * (red[0] + red[1] + red[2] + red[3]);
        __syncthreads();
        if (t < Mn) {
            const float* wr = &W[t*89];
            float a0 = 0.f, a1 = 0.f, a2 = 0.f;
            #pragma unroll
            for (int j = 0; j < 84; j += 3) {
                a0 += wr[j]*cur[j]; a1 += wr[j+1]*cur[j+1]; a2 += wr[j+2]*cur[j+2];
            }
            a0 += wr[84]*cur[84]; a1 += wr[85]*cur[85]; a2 += wr[86]*cur[86];
            nxt[t] = (a0 + a1 + a2) + s87 * zx;
        }
        __syncthreads();
    }
    float xf = (t < Mn) ? xA[t] : 0.f;
    float v2 = xf*xf;
    #pragma unroll
    for (int o = 16; o; o >>= 1) v2 += __shfl_down_sync(0xffffffffu, v2, o);
    if ((t & 31) == 0) red[t >> 5] = v2;
    __syncthreads();
    if (t == 0) zx = sqrtf(red[0] + red[1] + red[2] + red[3]);
    __syncthreads();
    if (t < Mn) g_vy[b*Mn + t] = v0s[t] + xf / fmaxf(zx, 1e-12f);
}

// ---------------- tensor-core conv (double-buffered bf16-split HMMA) ----------------
#define SA 24
__global__ void __launch_bounds__(256) conv_xl_tc(const float* __restrict__ x) {
    __shared__ __nv_bfloat16 Ah[2][64*SA], Al[2][64*SA], Bh[2][128*SA], Bl[2][128*SA];
    const int tid = threadIdx.x;
    const int m0 = blockIdx.x*64;
    const int warp = tid>>5, lane = tid&31;
    const int wm = warp & 3, wn = warp >> 2;
    const int g = lane>>2, t4 = lane&3;
    const int arow = tid & 63, ak = (tid>>6)<<2;
    const int m = m0 + arow;
    const float* xb = x + (size_t)(m/HWn)*(DOn*HWn) + (m%HWn);
    const int brow = tid>>1, bk8 = (tid&1)<<3;
    const __nv_bfloat16* whp = g_WhiT + (size_t)brow*DOn + bk8;
    const __nv_bfloat16* wlp = g_WloT + (size_t)brow*DOn + bk8;
    float acc[8][4] = {};
    float rx[4]; uint4 rh, rl;
    auto LDG = [&](int k0){
        #pragma unroll
        for (int i=0;i<4;i++) rx[i] = xb[(size_t)(k0+ak+i)*HWn];
        rh = *(const uint4*)(whp + k0);
        rl = *(const uint4*)(wlp + k0);
    };
    auto STS = [&](int buf){
        #pragma unroll
        for (int i=0;i<4;i++) {
            float v = rx[i];
            __nv_bfloat16 h = __float2bfloat16(v);
            Ah[buf][arow*SA + ak + i] = h;
            Al[buf][arow*SA + ak + i] = __float2bfloat16(v - __bfloat162float(h));
        }
        *(uint4*)&Bh[buf][brow*SA + bk8] = rh;
        *(uint4*)&Bl[buf][brow*SA + bk8] = rl;
    };
    LDG(0); STS(0); __syncthreads();
    const int ar0 = (wm*16+g)*SA + t4*2;
    const int ar1 = (wm*16+g+8)*SA + t4*2;
    for (int ks = 0; ks < 128; ks++) {
        int cur = ks & 1;
        if (ks+1 < 128) LDG((ks+1)<<4);
        unsigned ah0 = *(const unsigned*)&Ah[cur][ar0];
        unsigned ah1 = *(const unsigned*)&Ah[cur][ar1];
        unsigned ah2 = *(const unsigned*)&Ah[cur][ar0+8];
        unsigned ah3 = *(const unsigned*)&Ah[cur][ar1+8];
        unsigned al0 = *(const unsigned*)&Al[cur][ar0];
        unsigned al1 = *(const unsigned*)&Al[cur][ar1];
        unsigned al2 = *(const unsigned*)&Al[cur][ar0+8];
        unsigned al3 = *(const unsigned*)&Al[cur][ar1+8];
        #pragma unroll
        for (int f = 0; f < 8; f++) {
            int col = (wn*64 + f*8 + g)*SA + t4*2;
            unsigned bh0 = *(const unsigned*)&Bh[cur][col];
            unsigned bh1 = *(const unsigned*)&Bh[cur][col+8];
            unsigned bl0 = *(const unsigned*)&Bl[cur][col];
            unsigned bl1 = *(const unsigned*)&Bl[cur][col+8];
            MMA_BF16(acc[f], ah0,ah1,ah2,ah3, bh0,bh1);
            MMA_BF16(acc[f], ah0,ah1,ah2,ah3, bl0,bl1);
            MMA_BF16(acc[f], al0,al1,al2,al3, bh0,bh1);
        }
        if (ks+1 < 128) { STS(1-cur); __syncthreads(); }
    }
    const int mr = m0 + wm*16 + g;
    #pragma unroll
    for (int f = 0; f < 8; f++) {
        int cc = wn*64 + f*8 + t4*2;
        float2 bf = *(const float2*)&g_bef[cc];
        *(float2*)&g_xl2[(size_t)mr*DLn + cc]     = make_float2(acc[f][0]+bf.x, acc[f][1]+bf.y);
        *(float2*)&g_xl2[(size_t)(mr+8)*DLn + cc] = make_float2(acc[f][2]+bf.x, acc[f][3]+bf.y);
    }
}

// ---------------- G_e = Wg[:,:128] @ (node_p * v_y_e) ----------------
__global__ void k_G(const float* __restrict__ node_p, const float* __restrict__ Wg) {
    int q = blockIdx.x;
    int o0 = blockIdx.y * 16;
    int t = threadIdx.x;
    __shared__ float Nq[128*88];
    for (int idx = t; idx < 128*Mn; idx += 256) {
        int k = idx / Mn, mm = idx % Mn;
        Nq[k*88 + mm] = node_p[idx] * g_vy[(128*q + k)*Mn + mm];
    }
    __syncthreads();
    for (int idx = t; idx < 16*Mn; idx += 256) {
        int o = o0 + idx / Mn, mm = idx % Mn;
        const float* w = Wg + o*256;
        float acc = 0.f;
        #pragma unroll 8
        for (int k = 0; k < 128; k++) acc += w[k] * Nq[k*88 + mm];
        g_G[q*NM + o*Mn + mm] = acc;
    }
}

// ---------------- fused chain ----------------
#define C_R0 0
#define C_R1 11264
#define C_PS (C_R1 + 4576)
#define C_R2 22748
#define C_WG 34012
#define C_MS 50396
#define C_TOT 50652
#define CHAIN_SMEM (C_TOT*4)

__global__ void k_chain(const float* __restrict__ bg, const float* __restrict__ Ws,
                        const float* __restrict__ Wsp, const float* __restrict__ bsp) {
    extern __shared__ float S[];
    const int b = blockIdx.x, t = threadIdx.x, e = b & 1;
    float* m1s = S + C_R0;
    float* enS = S + C_R0;
    float* aS  = S + C_R1;
    float* psS = S + C_PS;
    float* gsT = S + C_R1;
    float* m2s = S + C_R2;
    float* WgS = S + C_WG;
    float* w   = S + C_MS;
    float* r   = S + C_MS + 88;
    __shared__ float mx, sm;

    const float* apsb = g_aps + (size_t)b*HWn;
    for (int i = t; i < Mn*HWn; i += 256) { int m=i/HWn, p=i%HWn; aS[m*52+p] = apsb[(size_t)m*NPIX + p]; }
    if (t < 52) aS[Mn*52 + t] = 0.f;
    for (int i = t; i < 128*HWn; i += 256) { int c=i/HWn, p=i%HWn; psS[c*52+p] = apsb[(size_t)(128+c)*NPIX + p]; }
    for (int i = t; i < 128*128/4; i += 256) ((float4*)WgS)[i] = ((const float4*)g_Wg2T)[i];
    __syncthreads();

    for (int u = t; u < 128*22; u += 256) {
        int c = u/22, mb = (u%22)*4;
        float a0=0.f,a1=0.f,a2=0.f,a3=0.f;
        const float* pr = psS + c*52;
        const float* ar = aS + mb*52;
        #pragma unroll
        for (int p = 0; p < HWn; p++) {
            float pv = pr[p];
            a0 += pv*ar[p]; a1 += pv*ar[52+p]; a2 += pv*ar[104+p]; a3 += pv*ar[156+p];
        }
        float* d = m1s + c*88 + mb;
        d[0]=fmaxf(a0,0.f); d[1]=fmaxf(a1,0.f); d[2]=fmaxf(a2,0.f); d[3]=fmaxf(a3,0.f);
    }
    __syncthreads();

    for (int u = t; u < Mn*32; u += 256) {
        int m = u%Mn, ob = (u/Mn)*4;
        float a0=0.f,a1=0.f,a2=0.f,a3=0.f;
        #pragma unroll 4
        for (int c = 0; c < 128; c++) {
            float mv = m1s[c*88+m];
            float4 wv = *(const float4*)&WgS[c*128+ob];
            a0 += wv.x*mv; a1 += wv.y*mv; a2 += wv.z*mv; a3 += wv.w*mv;
        }
        const float* Ge = g_G + e*NM;
        gsT[m*132+ob+0] = a0 + Ge[(ob+0)*Mn+m] + bg[ob+0];
        gsT[m*132+ob+1] = a1 + Ge[(ob+1)*Mn+m] + bg[ob+1];
        gsT[m*132+ob+2] = a2 + Ge[(ob+2)*Mn+m] + bg[ob+2];
        gsT[m*132+ob+3] = a3 + Ge[(ob+3)*Mn+m] + bg[ob+3];
    }
    __syncthreads();
    for (int i = t; i < Mn*Mn; i += 256) { int m=i/Mn, n=i%Mn; enS[m*88+n] = g_en[i]; }
    __syncthreads();

    for (int u = t; u < Mn*32; u += 256) {
        int n = u%Mn, cb = (u/Mn)*4;
        float a0=0.f,a1=0.f,a2=0.f,a3=0.f;
        #pragma unroll 4
        for (int m = 0; m < Mn; m++) {
            float ev = enS[m*88+n];
            float4 gv = *(const float4*)&gsT[m*132+cb];
            a0 += gv.x*ev; a1 += gv.y*ev; a2 += gv.z*ev; a3 += gv.w*ev;
        }
        m2s[(cb+0)*88+n]=fmaxf(a0,0.f);
        m2s[(cb+1)*88+n]=fmaxf(a1,0.f);
        m2s[(cb+2)*88+n]=fmaxf(a2,0.f);
        m2s[(cb+3)*88+n]=fmaxf(a3,0.f);
    }
    __syncthreads();

    if (t < Mn) {
        float acc = 0.f;
        #pragma unroll 8
        for (int c = 0; c < 128; c++) acc += Ws[c] * m2s[c*88+t];
        w[t] = acc;
    }
    __syncthreads();
    if (t == 0) { float m = -1e30f; for (int i = 0; i < Mn; i++) m = fmaxf(m, w[i]); mx = m; }
    __syncthreads();
    if (t < Mn) w[t] = expf(w[t] - mx);
    __syncthreads();
    if (t == 0) { float s = 0.f; for (int i = 0; i < Mn; i++) s += w[i]; sm = s; }
    __syncthreads();
    if (t < Mn) w[t] /= sm;
    __syncthreads();
    if (t < 128) {
        float acc = 0.f;
        #pragma unroll
        for (int m = 0; m < Mn; m++) acc += m2s[t*88+m] * w[m];
        r[t] = acc;
    }
    __syncthreads();
    if (t < 128) {
        float acc = bsp[t];
        const float* wr = Wsp + t*128;
        #pragma unroll 8
        for (int c = 0; c < 128; c++) acc += wr[c] * r[c];
        g_u[b*128 + t] = fmaxf(acc, 0.f);
    }
}

// ---------------- head ----------------
__global__ void k_head(const float* __restrict__ Wfc2, float* __restrict__ out) {
    int b = blockIdx.x, t = threadIdx.x;
    __shared__ float us[128];
    __shared__ float feat[BDn];
    __shared__ float lg[CLSn];
    __shared__ float mx, sm;
    if (t < 128) us[t] = g_u[b*128 + t];
    __syncthreads();
    {
        float fp = g_featp[b*BDn + t];
        float acc = g_biasaug[t] + fp;
        const float* w = g_Wcomb + t*128;
        #pragma unroll 8
        for (int c = 0; c < 128; c++) acc += w[c] * us[c];
        feat[t] = acc;
        out[OUT_FEAT + b*BDn + t] = acc;
        out[OUT_FEATP + b*BDn + t] = fp;
    }
    __syncthreads();
    if (t < CLSn) {
        float acc = 0.f;
        const float* w = Wfc2 + t*BDn;
        #pragma unroll 8
        for (int c = 0; c < BDn; c++) acc += w[c] * feat[c];
        lg[t] = acc;
        out[OUT_OUT2 + b*CLSn + t] = acc;
    }
    __syncthreads();
    if (t == 0) { float m = -1e30f; for (int i = 0; i < CLSn; i++) m = fmaxf(m, lg[i]); mx = m; }
    __syncthreads();
    if (t < CLSn) lg[t] = expf(lg[t] - mx);
    __syncthreads();
    if (t == 0) { float s = 0.f; for (int i = 0; i < CLSn; i++) s += lg[i]; sm = s; }
    __syncthreads();
    if (t < CLSn) out[OUT_SOFT + b*CLSn + t] = lg[t] / sm;
}

extern "C" void kernel_launch(void* const* d_in, const int* in_sizes, int n_in,
                              void* d_out, int out_size) {
    const float* x     = (const float*)d_in[0];
    const float* Wb    = (const float*)d_in[1];
    const float* bb    = (const float*)d_in[2];
    const float* Wfc   = (const float*)d_in[3];
    const float* Wfc2  = (const float*)d_in[4];
    const float* Wo1   = (const float*)d_in[5];
    const float* bo1   = (const float*)d_in[6];
    const float* Wo2   = (const float*)d_in[7];
    const float* bo2   = (const float*)d_in[8];
    const float* Wa    = (const float*)d_in[9];
    const float* ba    = (const float*)d_in[10];
    const float* Wps   = (const float*)d_in[11];
    const float* bps   = (const float*)d_in[12];
    const float* node_p= (const float*)d_in[13];
    const float* Wg    = (const float*)d_in[14];
    const float* bg    = (const float*)d_in[15];
    const float* Wsp   = (const float*)d_in[16];
    const float* bsp   = (const float*)d_in[17];
    const float* Ws    = (const float*)d_in[18];
    const float* Wox1  = (const float*)d_in[20];
    const float* box1  = (const float*)d_in[21];
    const float* Wox2  = (const float*)d_in[22];
    const float* box2  = (const float*)d_in[23];
    const float* edge  = (const float*)d_in[24];
    float* out = (float*)d_out;

    float* pZ     = nullptr; cudaGetSymbolAddress((void**)&pZ,     g_Z);
    float* pWcomb = nullptr; cudaGetSymbolAddress((void**)&pWcomb, g_Wcomb);
    float* pPart  = nullptr; cudaGetSymbolAddress((void**)&pPart,  g_part);
    float* pPartB = nullptr; cudaGetSymbolAddress((void**)&pPartB, g_partB);
    float* pXp    = nullptr; cudaGetSymbolAddress((void**)&pXp,    g_xp);
    float* pWap   = nullptr; cudaGetSymbolAddress((void**)&pWap,   g_Wap);
    float* pXl2   = nullptr; cudaGetSymbolAddress((void**)&pXl2,   g_xl2);
    float* pAps   = nullptr; cudaGetSymbolAddress((void**)&pAps,   g_aps);

    static cudaStream_t sA = nullptr, sB = nullptr;
    static cudaEvent_t eRoot, eB1, eAps, eW2;
    if (!sA) {
        cudaFuncSetAttribute(k_chain, cudaFuncAttributeMaxDynamicSharedMemorySize, CHAIN_SMEM);
        cudaStreamCreateWithFlags(&sA, cudaStreamNonBlocking);
        cudaStreamCreateWithFlags(&sB, cudaStreamNonBlocking);
        cudaEventCreateWithFlags(&eRoot, cudaEventDisableTiming);
        cudaEventCreateWithFlags(&eB1,   cudaEventDisableTiming);
        cudaEventCreateWithFlags(&eAps,  cudaEventDisableTiming);
        cudaEventCreateWithFlags(&eW2,   cudaEventDisableTiming);
    }

    // Fork side streams from the capturing stream FIRST (capture-legal),
    // then order kernel launches so conv_xl_tc is enqueue index 3 (profiled).
    cudaEventRecord(eRoot, 0);
    cudaStreamWaitEvent(sA, eRoot, 0);
    cudaStreamWaitEvent(sB, eRoot, 0);

    // ---- branch A ----
    gemm_wef_split<<<dim3(32,2), 256, 0, sA>>>(Wo1, Wo2);              // idx 0
    k_bias1<<<272, 256, 0, sA>>>(Wox2, box1, Wo2, bo1, bo2);           // idx 1
    cudaEventRecord(eB1, sA);
    k_prep_edge<<<1, 256>>>(edge);                                     // idx 2 (root)
    conv_xl_tc<<<196, 256, 0, sA>>>(x);                                // idx 3 <- profiled
    k_prep2<<<192, 256, 0, sA>>>(Wa, Wps, Wg);                         // idx 4
    gemm_db<0,1,false><<<dim3(4,196), 256, 0, sA>>>(pWap, pXl2, pAps, 256, NPIX, 128);
    cudaEventRecord(eAps, sA);

    // ---- branch B: Z -> Wcomb -> bias2 ----
    gemm_db<0,0,false><<<dim3(32,2), 256, 0, sB>>>(Wox2, Wox1, pZ, 2048, 128, 512);
    gemm_db<0,0,true><<<dim3(4,2,8), 256, 0, sB>>>(Wb, pZ, pPartB, 256, 128, 2048);
    k_reduce<<<128, 256, 0, sB>>>(pPartB, nullptr, pWcomb, 256*128, 128, 8);
    cudaStreamWaitEvent(sB, eB1, 0);
    k_bias2<<<32, 256, 0, sB>>>(Wb, box2, bb);
    cudaEventRecord(eW2, sB);

    // ---- root: xp -> featp -> preout(+reduce) -> pagerank -> G ----
    k_xp<<<65536, 256>>>(x);
    gemm_db<0,1,true><<<dim3(4,4,8), 256>>>(pXp, Wb, pPart, 256, 256, 2048);
    k_preout<<<256, 256>>>(Wfc, bb, out);
    k_pagerank<<<256, 128>>>();
    k_G<<<dim3(2,8), 256>>>(node_p, Wg);

    cudaStreamWaitEvent(0, eAps, 0);
    k_chain<<<256, 256, CHAIN_SMEM>>>(bg, Ws, Wsp, bsp);
    cudaStreamWaitEvent(0, eW2, 0);
    k_head<<<256, 256>>>(Wfc2, out);
}